// round 8
// baseline (speedup 1.0000x reference)
#include <cuda_runtime.h>
#include <math.h>
#include <stdint.h>

// ---------------- problem dims ----------------
#define Bn    8
#define Sq    1024
#define Cdim  640
#define Tctx  77
#define TPAD  96
#define CTXD  768
#define NHEAD 8
#define HSZ   80
#define FFD   5120
#define FFH   2560
#define Mrows (Bn * Sq)      // 8192
#define MCTX  (Bn * Tctx)    // 616

// ---------------- scratch ----------------
__device__ float g_ln  [(size_t)Mrows * Cdim];
__device__ float g_y   [(size_t)Mrows * Cdim];
__device__ float g_q   [(size_t)Mrows * Cdim];
__device__ float g_k   [(size_t)Mrows * Cdim];
__device__ float g_v   [(size_t)Mrows * Cdim];
__device__ float g_at  [(size_t)Mrows * Cdim];
__device__ float g_t   [(size_t)Mrows * Cdim];
__device__ float g_sc  [(size_t)64 * 1024 * 1024];
__device__ float g_ff  [(size_t)Mrows * FFD];
__device__ float g_gg  [(size_t)Mrows * FFH];

// ---------------- helpers ----------------
__device__ __forceinline__ void mma_tf32(float* c, const uint32_t* a, const uint32_t* b)
{
    asm volatile(
        "mma.sync.aligned.m16n8k8.row.col.f32.tf32.tf32.f32 "
        "{%0,%1,%2,%3}, {%4,%5,%6,%7}, {%8,%9}, {%0,%1,%2,%3};"
        : "+f"(c[0]), "+f"(c[1]), "+f"(c[2]), "+f"(c[3])
        : "r"(a[0]), "r"(a[1]), "r"(a[2]), "r"(a[3]), "r"(b[0]), "r"(b[1]));
}

__device__ __forceinline__ void cp16(uint32_t dst, const void* src, bool pred)
{
    const int sz = pred ? 16 : 0;
    asm volatile("cp.async.cg.shared.global [%0], [%1], 16, %2;\n"
                 :: "r"(dst), "l"(src), "r"(sz));
}
__device__ __forceinline__ void cp_commit() { asm volatile("cp.async.commit_group;\n"); }
template <int N>
__device__ __forceinline__ void cp_wait() { asm volatile("cp.async.wait_group %0;\n" :: "n"(N)); }

__device__ __forceinline__ uint32_t fu(float f) { return __float_as_uint(f); }

// ---------------- GroupNorm ----------------
__global__ void groupnorm_kernel(const float* __restrict__ x,
                                 const float* __restrict__ gamma,
                                 const float* __restrict__ beta,
                                 float* __restrict__ out)
{
    const int b = blockIdx.x >> 5;
    const int g = blockIdx.x & 31;
    const float* base = x + (size_t)b * Sq * Cdim + g * 20;
    float sum = 0.f, sq = 0.f;
    for (int idx = threadIdx.x; idx < Sq * 20; idx += 256) {
        int hw = idx / 20, c = idx % 20;
        float v = base[(size_t)hw * Cdim + c];
        sum += v; sq += v * v;
    }
    #pragma unroll
    for (int o = 16; o > 0; o >>= 1) {
        sum += __shfl_xor_sync(0xffffffffu, sum, o);
        sq  += __shfl_xor_sync(0xffffffffu, sq,  o);
    }
    __shared__ float s1[8], s2[8];
    const int wid = threadIdx.x >> 5, lane = threadIdx.x & 31;
    if (lane == 0) { s1[wid] = sum; s2[wid] = sq; }
    __syncthreads();
    float tot = 0.f, totq = 0.f;
    #pragma unroll
    for (int i = 0; i < 8; i++) { tot += s1[i]; totq += s2[i]; }
    const float mean = tot * (1.f / 20480.f);
    const float var  = totq * (1.f / 20480.f) - mean * mean;
    const float rstd = rsqrtf(var + 1e-5f);
    float* ob = out + (size_t)b * Sq * Cdim + g * 20;
    for (int idx = threadIdx.x; idx < Sq * 20; idx += 256) {
        int hw = idx / 20, c = idx % 20;
        float v = base[(size_t)hw * Cdim + c];
        ob[(size_t)hw * Cdim + c] = (v - mean) * rstd * gamma[g * 20 + c] + beta[g * 20 + c];
    }
}

// ---------------- LayerNorm ----------------
__global__ void layernorm_kernel(const float* __restrict__ x,
                                 const float* __restrict__ g,
                                 const float* __restrict__ b,
                                 float* __restrict__ out, int rows)
{
    const int w = (blockIdx.x << 3) + (threadIdx.x >> 5);
    if (w >= rows) return;
    const int lane = threadIdx.x & 31;
    const float* row = x + (size_t)w * Cdim;
    float4 v[5];
    float sum = 0.f, sq = 0.f;
    #pragma unroll
    for (int p = 0; p < 5; p++) {
        v[p] = *reinterpret_cast<const float4*>(row + (lane + 32 * p) * 4);
        sum += v[p].x + v[p].y + v[p].z + v[p].w;
        sq  += v[p].x * v[p].x + v[p].y * v[p].y + v[p].z * v[p].z + v[p].w * v[p].w;
    }
    #pragma unroll
    for (int o = 16; o > 0; o >>= 1) {
        sum += __shfl_xor_sync(0xffffffffu, sum, o);
        sq  += __shfl_xor_sync(0xffffffffu, sq,  o);
    }
    const float mean = sum * (1.f / 640.f);
    const float var  = sq * (1.f / 640.f) - mean * mean;
    const float rstd = rsqrtf(var + 1e-5f);
    float* orow = out + (size_t)w * Cdim;
    #pragma unroll
    for (int p = 0; p < 5; p++) {
        const int off = (lane + 32 * p) * 4;
        const float4 g4 = *reinterpret_cast<const float4*>(g + off);
        const float4 b4 = *reinterpret_cast<const float4*>(b + off);
        float4 o;
        o.x = (v[p].x - mean) * rstd * g4.x + b4.x;
        o.y = (v[p].y - mean) * rstd * g4.y + b4.y;
        o.z = (v[p].z - mean) * rstd * g4.z + b4.z;
        o.w = (v[p].w - mean) * rstd * g4.w + b4.w;
        *reinterpret_cast<float4*>(orow + off) = o;
    }
}

// ---------------- pipelined TF32 GEMM ----------------
// 128x128x32 block tile, 4 warps (2x2), warp tile 64x64.
// 3-stage cp.async ring, one __syncthreads per k-tile (prefetch AFTER barrier).
#define ASP 36     // As pitch: frag bank = 4g+tig -> conflict-free
#define BSP 136    // Bs pitch: frag bank = 8tig+g -> conflict-free
#define ASTG (128 * ASP)
#define BSTG (32 * BSP)
#define NSTAGE 3
#define GEMM_SMEM ((NSTAGE * ASTG + NSTAGE * BSTG) * 4)

__global__ __launch_bounds__(128, 2)
void tf32_gemm_kernel(const float* __restrict__ A, const float* __restrict__ B,
                      const float* __restrict__ bias, const float* __restrict__ Res,
                      float* __restrict__ C, int M, int N, int K)
{
    extern __shared__ float smem[];
    float* As = smem;                        // [NSTAGE][128*ASP]
    float* Bs = smem + NSTAGE * ASTG;        // [NSTAGE][32*BSP]
    const int tid  = threadIdx.x;
    const int lane = tid & 31, warp = tid >> 5;
    const int g = lane >> 2, tig = lane & 3;
    const int wm = (warp >> 1) * 64;
    const int wn = (warp & 1) * 64;
    const int row0 = blockIdx.y * 128, col0 = blockIdx.x * 128;

    // staging maps (128 threads)
    const int am = tid;                      // A: one row per thread (8 x cp16)
    const int bk = tid >> 2, bn = (tid & 3) * 32;  // B: row bk, 32 floats (8 x cp16)
    const bool arow_ok = (row0 + am) < M;
    const float* agp = A + (size_t)(row0 + am) * K;
    const float* bgp = B + (size_t)bk * N + col0 + bn;
    const uint32_t as_d = (uint32_t)__cvta_generic_to_shared(As + am * ASP);
    const uint32_t bs_d = (uint32_t)__cvta_generic_to_shared(Bs + bk * BSP + bn);

    float acc[4][8][4];
    #pragma unroll
    for (int mt = 0; mt < 4; mt++)
        #pragma unroll
        for (int nt = 0; nt < 8; nt++)
            #pragma unroll
            for (int i = 0; i < 4; i++) acc[mt][nt][i] = 0.f;

    const int KT = K >> 5;

    // prologue: stage 0 and 1
    #pragma unroll
    for (int p = 0; p < 2; p++) {
        if (p < KT) {
            const float* ag = agp + p * 32;
            const float* bg = bgp + (size_t)p * 32 * N;
            #pragma unroll
            for (int l = 0; l < 8; l++)
                cp16(as_d + (uint32_t)(p * ASTG * 4) + l * 16, ag + l * 4, arow_ok);
            #pragma unroll
            for (int l = 0; l < 8; l++)
                cp16(bs_d + (uint32_t)(p * BSTG * 4) + l * 16, bg + l * 4, true);
        }
        cp_commit();
    }

    int s = 0;          // current compute stage
    int sw = 2;         // next write stage
    for (int kt = 0; kt < KT; kt++) {
        cp_wait<1>();
        __syncthreads();

        // prefetch kt+2 into stage sw (safe: stage sw last read at iter kt-1)
        if (kt + 2 < KT) {
            const float* ag = agp + (kt + 2) * 32;
            const float* bg = bgp + (size_t)(kt + 2) * 32 * N;
            const uint32_t ad = as_d + (uint32_t)(sw * ASTG * 4);
            const uint32_t bd = bs_d + (uint32_t)(sw * BSTG * 4);
            #pragma unroll
            for (int l = 0; l < 8; l++) cp16(ad + l * 16, ag + l * 4, arow_ok);
            #pragma unroll
            for (int l = 0; l < 8; l++) cp16(bd + l * 16, bg + l * 4, true);
        }
        cp_commit();

        const float* as = As + s * ASTG;
        const float* bs = Bs + s * BSTG;
        #pragma unroll
        for (int ks = 0; ks < 4; ks++) {
            const int kq = ks * 8 + tig;
            uint32_t af[4][4];
            #pragma unroll
            for (int mt = 0; mt < 4; mt++) {
                const int m = wm + mt * 16 + g;
                af[mt][0] = fu(as[m * ASP + kq]);
                af[mt][1] = fu(as[(m + 8) * ASP + kq]);
                af[mt][2] = fu(as[m * ASP + kq + 4]);
                af[mt][3] = fu(as[(m + 8) * ASP + kq + 4]);
            }
            uint32_t bf[8][2];
            #pragma unroll
            for (int nt = 0; nt < 8; nt++) {
                const int n = wn + nt * 8 + g;
                bf[nt][0] = fu(bs[kq * BSP + n]);
                bf[nt][1] = fu(bs[(kq + 4) * BSP + n]);
            }
            #pragma unroll
            for (int mt = 0; mt < 4; mt++)
                #pragma unroll
                for (int nt = 0; nt < 8; nt++)
                    mma_tf32(acc[mt][nt], af[mt], bf[nt]);
        }

        s = (s == NSTAGE - 1) ? 0 : s + 1;
        sw = (sw == NSTAGE - 1) ? 0 : sw + 1;
    }

    // epilogue
    #pragma unroll
    for (int mt = 0; mt < 4; mt++) {
        const int r0 = row0 + wm + mt * 16 + g;
        const int r1 = r0 + 8;
        #pragma unroll
        for (int nt = 0; nt < 8; nt++) {
            const int c = col0 + wn + nt * 8 + 2 * tig;
            float2 v0 = make_float2(acc[mt][nt][0], acc[mt][nt][1]);
            float2 v1 = make_float2(acc[mt][nt][2], acc[mt][nt][3]);
            if (bias) {
                const float2 bb = *reinterpret_cast<const float2*>(bias + c);
                v0.x += bb.x; v0.y += bb.y;
                v1.x += bb.x; v1.y += bb.y;
            }
            if (r0 < M) {
                if (Res) {
                    const float2 rv = *reinterpret_cast<const float2*>(Res + (size_t)r0 * N + c);
                    v0.x += rv.x; v0.y += rv.y;
                }
                *reinterpret_cast<float2*>(C + (size_t)r0 * N + c) = v0;
            }
            if (r1 < M) {
                if (Res) {
                    const float2 rv = *reinterpret_cast<const float2*>(Res + (size_t)r1 * N + c);
                    v1.x += rv.x; v1.y += rv.y;
                }
                *reinterpret_cast<float2*>(C + (size_t)r1 * N + c) = v1;
            }
        }
    }
}

// ---------------- MMA attention scores ----------------
#define QP 84
__global__ __launch_bounds__(128)
void attn_scores_mma(const float* __restrict__ Q, const float* __restrict__ Kb,
                     float* __restrict__ S, int Tk, int Tpad, int kSeq)
{
    __shared__ float Qs[64 * QP];
    __shared__ float Ks[64 * QP];
    const int bh = blockIdx.z, b = bh >> 3, n = bh & 7;
    const float* qb = Q + (size_t)b * Sq * Cdim + n * HSZ;
    const float* kb = Kb + (size_t)b * kSeq * Cdim + n * HSZ;
    float* sb = S + (size_t)bh * Sq * Tpad;
    const int i0 = blockIdx.y * 64, j0 = blockIdx.x * 64;
    const int tid = threadIdx.x;

    for (int e = tid; e < 64 * 20; e += 128) {
        const int r = e / 20, c = (e % 20) * 4;
        const float4 qv = *reinterpret_cast<const float4*>(qb + (size_t)(i0 + r) * Cdim + c);
        *reinterpret_cast<float4*>(&Qs[r * QP + c]) = qv;
        float4 kv = make_float4(0.f, 0.f, 0.f, 0.f);
        if (j0 + r < Tk)
            kv = *reinterpret_cast<const float4*>(kb + (size_t)(j0 + r) * Cdim + c);
        *reinterpret_cast<float4*>(&Ks[r * QP + c]) = kv;
    }
    __syncthreads();

    const int lane = tid & 31, warp = tid >> 5;
    const int g = lane >> 2, tig = lane & 3;
    const int wm = (warp >> 1) * 32, wn = (warp & 1) * 32;

    float acc[2][4][4];
    #pragma unroll
    for (int mt = 0; mt < 2; mt++)
        #pragma unroll
        for (int nt = 0; nt < 4; nt++)
            #pragma unroll
            for (int i = 0; i < 4; i++) acc[mt][nt][i] = 0.f;

    #pragma unroll
    for (int ks = 0; ks < 10; ks++) {
        const int kq = ks * 8 + tig;
        uint32_t af[2][4];
        #pragma unroll
        for (int mt = 0; mt < 2; mt++) {
            const int m = wm + mt * 16 + g;
            af[mt][0] = fu(Qs[m * QP + kq]);
            af[mt][1] = fu(Qs[(m + 8) * QP + kq]);
            af[mt][2] = fu(Qs[m * QP + kq + 4]);
            af[mt][3] = fu(Qs[(m + 8) * QP + kq + 4]);
        }
        uint32_t bf[4][2];
        #pragma unroll
        for (int nt = 0; nt < 4; nt++) {
            const int nn = wn + nt * 8 + g;
            bf[nt][0] = fu(Ks[nn * QP + kq]);
            bf[nt][1] = fu(Ks[nn * QP + kq + 4]);
        }
        #pragma unroll
        for (int mt = 0; mt < 2; mt++)
            #pragma unroll
            for (int nt = 0; nt < 4; nt++)
                mma_tf32(acc[mt][nt], af[mt], bf[nt]);
    }

    const float scale = 0.11180339887498949f;
    #pragma unroll
    for (int mt = 0; mt < 2; mt++) {
        const int r0 = i0 + wm + mt * 16 + g;
        const int r1 = r0 + 8;
        #pragma unroll
        for (int nt = 0; nt < 4; nt++) {
            const int c = j0 + wn + nt * 8 + 2 * tig;
            if (c < Tk)     { sb[(size_t)r0 * Tpad + c]     = acc[mt][nt][0] * scale;
                              sb[(size_t)r1 * Tpad + c]     = acc[mt][nt][2] * scale; }
            if (c + 1 < Tk) { sb[(size_t)r0 * Tpad + c + 1] = acc[mt][nt][1] * scale;
                              sb[(size_t)r1 * Tpad + c + 1] = acc[mt][nt][3] * scale; }
        }
    }
}

// ---------------- softmax (padded) ----------------
__global__ void softmax_kernel(float* __restrict__ S, int rows, int L, int Lpad)
{
    const int w = (blockIdx.x << 3) + (threadIdx.x >> 5);
    if (w >= rows) return;
    const int lane = threadIdx.x & 31;
    float* row = S + (size_t)w * Lpad;
    float v[32];
    float m = -3.4e38f;
    #pragma unroll
    for (int p = 0; p < 32; p++) {
        const int i = lane + (p << 5);
        v[p] = (i < L) ? row[i] : -3.4e38f;
        m = fmaxf(m, v[p]);
    }
    #pragma unroll
    for (int o = 16; o > 0; o >>= 1) m = fmaxf(m, __shfl_xor_sync(0xffffffffu, m, o));
    float s = 0.f;
    #pragma unroll
    for (int p = 0; p < 32; p++) {
        const int i = lane + (p << 5);
        if (i < L) { v[p] = __expf(v[p] - m); s += v[p]; }
    }
    #pragma unroll
    for (int o = 16; o > 0; o >>= 1) s += __shfl_xor_sync(0xffffffffu, s, o);
    const float inv = 1.f / s;
    #pragma unroll
    for (int p = 0; p < 32; p++) {
        const int i = lane + (p << 5);
        if (i < L) row[i] = v[p] * inv;
        else if (i < Lpad) row[i] = 0.f;
    }
}

// ---------------- MMA attention PV ----------------
#define PP 36
#define VP 88
__global__ __launch_bounds__(256)
void attn_pv_mma(const float* __restrict__ P, const float* __restrict__ V,
                 float* __restrict__ O, int Tk, int Tpad, int vSeq)
{
    __shared__ float Ps[128 * PP];
    __shared__ float Vs[32 * VP];
    const int bh = blockIdx.z, b = bh >> 3, n = bh & 7;
    const float* pb = P + (size_t)bh * Sq * Tpad;
    const float* vb = V + (size_t)b * vSeq * Cdim + n * HSZ;
    float* ob = O + (size_t)b * Sq * Cdim + n * HSZ;
    const int i0 = blockIdx.x * 128;
    const int tid = threadIdx.x;
    const int lane = tid & 31, warp = tid >> 5;
    const int g = lane >> 2, tig = lane & 3;
    const int wm = (warp >> 1) * 32, wn = (warp & 1) * 40;

    const int pr = tid >> 1, pc = (tid & 1) * 16;

    float acc[2][5][4];
    #pragma unroll
    for (int mt = 0; mt < 2; mt++)
        #pragma unroll
        for (int nt = 0; nt < 5; nt++)
            #pragma unroll
            for (int i = 0; i < 4; i++) acc[mt][nt][i] = 0.f;

    for (int t0 = 0; t0 < Tpad; t0 += 32) {
        #pragma unroll
        for (int l = 0; l < 4; l++) {
            const float4 pv = *reinterpret_cast<const float4*>(
                pb + (size_t)(i0 + pr) * Tpad + t0 + pc + l * 4);
            *reinterpret_cast<float4*>(&Ps[pr * PP + pc + l * 4]) = pv;
        }
        for (int e = tid; e < 32 * 20; e += 256) {
            const int kr = e / 20, c = (e % 20) * 4;
            float4 vv = make_float4(0.f, 0.f, 0.f, 0.f);
            if (t0 + kr < Tk)
                vv = *reinterpret_cast<const float4*>(vb + (size_t)(t0 + kr) * Cdim + c);
            *reinterpret_cast<float4*>(&Vs[kr * VP + c]) = vv;
        }
        __syncthreads();

        #pragma unroll
        for (int ks = 0; ks < 4; ks++) {
            const int kq = ks * 8 + tig;
            uint32_t af[2][4];
            #pragma unroll
            for (int mt = 0; mt < 2; mt++) {
                const int m = wm + mt * 16 + g;
                af[mt][0] = fu(Ps[m * PP + kq]);
                af[mt][1] = fu(Ps[(m + 8) * PP + kq]);
                af[mt][2] = fu(Ps[m * PP + kq + 4]);
                af[mt][3] = fu(Ps[(m + 8) * PP + kq + 4]);
            }
            uint32_t bf[5][2];
            #pragma unroll
            for (int nt = 0; nt < 5; nt++) {
                const int nn = wn + nt * 8 + g;
                bf[nt][0] = fu(Vs[kq * VP + nn]);
                bf[nt][1] = fu(Vs[(kq + 4) * VP + nn]);
            }
            #pragma unroll
            for (int mt = 0; mt < 2; mt++)
                #pragma unroll
                for (int nt = 0; nt < 5; nt++)
                    mma_tf32(acc[mt][nt], af[mt], bf[nt]);
        }
        __syncthreads();
    }

    #pragma unroll
    for (int mt = 0; mt < 2; mt++) {
        const int r0 = i0 + wm + mt * 16 + g;
        const int r1 = r0 + 8;
        #pragma unroll
        for (int nt = 0; nt < 5; nt++) {
            const int c = wn + nt * 8 + 2 * tig;
            *reinterpret_cast<float2*>(ob + (size_t)r0 * Cdim + c) =
                make_float2(acc[mt][nt][0], acc[mt][nt][1]);
            *reinterpret_cast<float2*>(ob + (size_t)r1 * Cdim + c) =
                make_float2(acc[mt][nt][2], acc[mt][nt][3]);
        }
    }
}

// ---------------- GEGLU ----------------
__device__ __forceinline__ float geglu_one(float xh, float g)
{
    const float t = tanhf(g * 0.7978845608f * (1.f + 0.044715f * g * g));
    return xh * 0.5f * g * (1.f + t);
}

__global__ void geglu_kernel(const float* __restrict__ ff, float* __restrict__ out)
{
    const size_t idx = (size_t)blockIdx.x * blockDim.x + threadIdx.x;
    if (idx >= (size_t)Mrows * (FFH / 4)) return;
    const size_t row = idx / (FFH / 4);
    const int c4 = (int)(idx % (FFH / 4));
    const float4 xh = *reinterpret_cast<const float4*>(ff + row * FFD + c4 * 4);
    const float4 gt = *reinterpret_cast<const float4*>(ff + row * FFD + FFH + c4 * 4);
    float4 o;
    o.x = geglu_one(xh.x, gt.x);
    o.y = geglu_one(xh.y, gt.y);
    o.z = geglu_one(xh.z, gt.z);
    o.w = geglu_one(xh.w, gt.w);
    *reinterpret_cast<float4*>(out + row * FFH + c4 * 4) = o;
}

// ---------------- host orchestration ----------------
extern "C" void kernel_launch(void* const* d_in, const int* in_sizes, int n_in,
                              void* d_out, int out_size)
{
    (void)in_sizes; (void)n_in; (void)out_size;
    const float* x     = (const float*)d_in[0];
    const float* ctx   = (const float*)d_in[1];
    const float* gn_g  = (const float*)d_in[2];
    const float* gn_b  = (const float*)d_in[3];
    const float* piw   = (const float*)d_in[4];
    const float* pib   = (const float*)d_in[5];
    const float* ln1g  = (const float*)d_in[6];
    const float* ln1b  = (const float*)d_in[7];
    const float* a1q   = (const float*)d_in[8];
    const float* a1k   = (const float*)d_in[9];
    const float* a1v   = (const float*)d_in[10];
    const float* a1o   = (const float*)d_in[11];
    const float* a1ob  = (const float*)d_in[12];
    const float* ln2g  = (const float*)d_in[13];
    const float* ln2b  = (const float*)d_in[14];
    const float* a2q   = (const float*)d_in[15];
    const float* a2k   = (const float*)d_in[16];
    const float* a2v   = (const float*)d_in[17];
    const float* a2o   = (const float*)d_in[18];
    const float* a2ob  = (const float*)d_in[19];
    const float* ln3g  = (const float*)d_in[20];
    const float* ln3b  = (const float*)d_in[21];
    const float* ff1w  = (const float*)d_in[22];
    const float* ff1b  = (const float*)d_in[23];
    const float* ff2w  = (const float*)d_in[24];
    const float* ff2b  = (const float*)d_in[25];
    const float* prw   = (const float*)d_in[26];
    const float* prb   = (const float*)d_in[27];
    float* out = (float*)d_out;

    float *ln, *y, *q, *k, *v, *at, *t, *sc, *ff, *gg;
    cudaGetSymbolAddress((void**)&ln, g_ln);
    cudaGetSymbolAddress((void**)&y,  g_y);
    cudaGetSymbolAddress((void**)&q,  g_q);
    cudaGetSymbolAddress((void**)&k,  g_k);
    cudaGetSymbolAddress((void**)&v,  g_v);
    cudaGetSymbolAddress((void**)&at, g_at);
    cudaGetSymbolAddress((void**)&t,  g_t);
    cudaGetSymbolAddress((void**)&sc, g_sc);
    cudaGetSymbolAddress((void**)&ff, g_ff);
    cudaGetSymbolAddress((void**)&gg, g_gg);

    cudaFuncSetAttribute(tf32_gemm_kernel,
                         cudaFuncAttributeMaxDynamicSharedMemorySize, GEMM_SMEM);

    const dim3 gemm640(Cdim / 128, Mrows / 128);
    const dim3 gemmCtx(Cdim / 128, (MCTX + 127) / 128);
    const dim3 gemmFF(FFD / 128, Mrows / 128);

    // y = proj_in(group_norm(x))
    groupnorm_kernel<<<Bn * 32, 256>>>(x, gn_g, gn_b, ln);
    tf32_gemm_kernel<<<gemm640, 128, GEMM_SMEM>>>(ln, piw, pib, nullptr, y, Mrows, Cdim, Cdim);

    // self attention
    layernorm_kernel<<<Mrows / 8, 256>>>(y, ln1g, ln1b, ln, Mrows);
    tf32_gemm_kernel<<<gemm640, 128, GEMM_SMEM>>>(ln, a1q, nullptr, nullptr, q, Mrows, Cdim, Cdim);
    tf32_gemm_kernel<<<gemm640, 128, GEMM_SMEM>>>(ln, a1k, nullptr, nullptr, k, Mrows, Cdim, Cdim);
    tf32_gemm_kernel<<<gemm640, 128, GEMM_SMEM>>>(ln, a1v, nullptr, nullptr, v, Mrows, Cdim, Cdim);
    attn_scores_mma<<<dim3(16, 16, 64), 128>>>(q, k, sc, Sq, Sq, Sq);
    softmax_kernel<<<(64 * Sq) / 8, 256>>>(sc, 64 * Sq, Sq, Sq);
    attn_pv_mma<<<dim3(8, 1, 64), 256>>>(sc, v, at, Sq, Sq, Sq);
    tf32_gemm_kernel<<<gemm640, 128, GEMM_SMEM>>>(at, a1o, a1ob, y, t, Mrows, Cdim, Cdim);

    // cross attention
    layernorm_kernel<<<Mrows / 8, 256>>>(t, ln2g, ln2b, ln, Mrows);
    tf32_gemm_kernel<<<gemmCtx, 128, GEMM_SMEM>>>(ctx, a2k, nullptr, nullptr, k, MCTX, Cdim, CTXD);
    tf32_gemm_kernel<<<gemmCtx, 128, GEMM_SMEM>>>(ctx, a2v, nullptr, nullptr, v, MCTX, Cdim, CTXD);
    tf32_gemm_kernel<<<gemm640, 128, GEMM_SMEM>>>(ln, a2q, nullptr, nullptr, q, Mrows, Cdim, Cdim);
    attn_scores_mma<<<dim3(2, 16, 64), 128>>>(q, k, sc, Tctx, TPAD, Tctx);
    softmax_kernel<<<(64 * Sq) / 8, 256>>>(sc, 64 * Sq, Tctx, TPAD);
    attn_pv_mma<<<dim3(8, 1, 64), 256>>>(sc, v, at, Tctx, TPAD, Tctx);
    tf32_gemm_kernel<<<gemm640, 128, GEMM_SMEM>>>(at, a2o, a2ob, t, t, Mrows, Cdim, Cdim);

    // GEGLU feed-forward
    layernorm_kernel<<<Mrows / 8, 256>>>(t, ln3g, ln3b, ln, Mrows);
    tf32_gemm_kernel<<<gemmFF, 128, GEMM_SMEM>>>(ln, ff1w, ff1b, nullptr, ff, Mrows, FFD, Cdim);
    geglu_kernel<<<(Mrows * (FFH / 4)) / 256, 256>>>(ff, gg);
    tf32_gemm_kernel<<<gemm640, 128, GEMM_SMEM>>>(gg, ff2w, ff2b, t, t, Mrows, Cdim, FFH);

    // proj_out + input residual
    tf32_gemm_kernel<<<gemm640, 128, GEMM_SMEM>>>(t, prw, prb, x, out, Mrows, Cdim, Cdim);
}

// round 10
// speedup vs baseline: 1.1427x; 1.1427x over previous
#include <cuda_runtime.h>
#include <math.h>
#include <stdint.h>

// ---------------- problem dims ----------------
#define Bn    8
#define Sq    1024
#define Cdim  640
#define Tctx  77
#define TPAD  96
#define CTXD  768
#define NHEAD 8
#define HSZ   80
#define FFD   5120
#define FFH   2560
#define Mrows (Bn * Sq)      // 8192
#define MCTX  (Bn * Tctx)    // 616

// ---------------- scratch ----------------
__device__ float g_ln  [(size_t)Mrows * Cdim];
__device__ float g_y   [(size_t)Mrows * Cdim];
__device__ float g_q   [(size_t)Mrows * Cdim];
__device__ float g_at  [(size_t)Mrows * Cdim];
__device__ float g_t   [(size_t)Mrows * Cdim];
__device__ float g_sc  [(size_t)64 * 1024 * 1024];
__device__ float g_ff  [(size_t)Mrows * FFD];
__device__ float g_gg  [(size_t)Mrows * FFH];
__device__ float g_qkv [(size_t)Mrows * 1920];
__device__ float g_kv  [(size_t)MCTX * 1280];
__device__ float g_wp  [(size_t)Cdim * 1920];
__device__ float g_wc  [(size_t)CTXD * 1280];

// ---------------- helpers ----------------
__device__ __forceinline__ void mma_tf32(float* c, const uint32_t* a, const uint32_t* b)
{
    asm volatile(
        "mma.sync.aligned.m16n8k8.row.col.f32.tf32.tf32.f32 "
        "{%0,%1,%2,%3}, {%4,%5,%6,%7}, {%8,%9}, {%0,%1,%2,%3};"
        : "+f"(c[0]), "+f"(c[1]), "+f"(c[2]), "+f"(c[3])
        : "r"(a[0]), "r"(a[1]), "r"(a[2]), "r"(a[3]), "r"(b[0]), "r"(b[1]));
}

__device__ __forceinline__ void cp16(uint32_t dst, const void* src, bool pred)
{
    const int sz = pred ? 16 : 0;
    asm volatile("cp.async.cg.shared.global [%0], [%1], 16, %2;\n"
                 :: "r"(dst), "l"(src), "r"(sz));
}
__device__ __forceinline__ void cp_commit() { asm volatile("cp.async.commit_group;\n"); }
template <int N>
__device__ __forceinline__ void cp_wait() { asm volatile("cp.async.wait_group %0;\n" :: "n"(N)); }

__device__ __forceinline__ uint32_t fu(float f) { return __float_as_uint(f); }

// ---------------- weight packing ----------------
__global__ void pack3_kernel(const float* __restrict__ w0, const float* __restrict__ w1,
                             const float* __restrict__ w2, float* __restrict__ out, int rows)
{
    const int total = rows * (Cdim / 4);
    for (int i = blockIdx.x * blockDim.x + threadIdx.x; i < total; i += gridDim.x * blockDim.x) {
        const int r = i / (Cdim / 4), c4 = i % (Cdim / 4);
        const float4 v0 = *reinterpret_cast<const float4*>(w0 + (size_t)r * Cdim + c4 * 4);
        const float4 v1 = *reinterpret_cast<const float4*>(w1 + (size_t)r * Cdim + c4 * 4);
        const float4 v2 = *reinterpret_cast<const float4*>(w2 + (size_t)r * Cdim + c4 * 4);
        *reinterpret_cast<float4*>(out + (size_t)r * 1920 + c4 * 4) = v0;
        *reinterpret_cast<float4*>(out + (size_t)r * 1920 + 640 + c4 * 4) = v1;
        *reinterpret_cast<float4*>(out + (size_t)r * 1920 + 1280 + c4 * 4) = v2;
    }
}

__global__ void pack2_kernel(const float* __restrict__ w0, const float* __restrict__ w1,
                             float* __restrict__ out, int rows)
{
    const int total = rows * (Cdim / 4);
    for (int i = blockIdx.x * blockDim.x + threadIdx.x; i < total; i += gridDim.x * blockDim.x) {
        const int r = i / (Cdim / 4), c4 = i % (Cdim / 4);
        const float4 v0 = *reinterpret_cast<const float4*>(w0 + (size_t)r * Cdim + c4 * 4);
        const float4 v1 = *reinterpret_cast<const float4*>(w1 + (size_t)r * Cdim + c4 * 4);
        *reinterpret_cast<float4*>(out + (size_t)r * 1280 + c4 * 4) = v0;
        *reinterpret_cast<float4*>(out + (size_t)r * 1280 + 640 + c4 * 4) = v1;
    }
}

// ---------------- GroupNorm ----------------
__global__ void groupnorm_kernel(const float* __restrict__ x,
                                 const float* __restrict__ gamma,
                                 const float* __restrict__ beta,
                                 float* __restrict__ out)
{
    const int b = blockIdx.x >> 5;
    const int g = blockIdx.x & 31;
    const float* base = x + (size_t)b * Sq * Cdim + g * 20;
    float sum = 0.f, sq = 0.f;
    for (int idx = threadIdx.x; idx < Sq * 20; idx += 256) {
        int hw = idx / 20, c = idx % 20;
        float v = base[(size_t)hw * Cdim + c];
        sum += v; sq += v * v;
    }
    #pragma unroll
    for (int o = 16; o > 0; o >>= 1) {
        sum += __shfl_xor_sync(0xffffffffu, sum, o);
        sq  += __shfl_xor_sync(0xffffffffu, sq,  o);
    }
    __shared__ float s1[8], s2[8];
    const int wid = threadIdx.x >> 5, lane = threadIdx.x & 31;
    if (lane == 0) { s1[wid] = sum; s2[wid] = sq; }
    __syncthreads();
    float tot = 0.f, totq = 0.f;
    #pragma unroll
    for (int i = 0; i < 8; i++) { tot += s1[i]; totq += s2[i]; }
    const float mean = tot * (1.f / 20480.f);
    const float var  = totq * (1.f / 20480.f) - mean * mean;
    const float rstd = rsqrtf(var + 1e-5f);
    float* ob = out + (size_t)b * Sq * Cdim + g * 20;
    for (int idx = threadIdx.x; idx < Sq * 20; idx += 256) {
        int hw = idx / 20, c = idx % 20;
        float v = base[(size_t)hw * Cdim + c];
        ob[(size_t)hw * Cdim + c] = (v - mean) * rstd * gamma[g * 20 + c] + beta[g * 20 + c];
    }
}

// ---------------- LayerNorm ----------------
__global__ void layernorm_kernel(const float* __restrict__ x,
                                 const float* __restrict__ g,
                                 const float* __restrict__ b,
                                 float* __restrict__ out, int rows)
{
    const int w = (blockIdx.x << 3) + (threadIdx.x >> 5);
    if (w >= rows) return;
    const int lane = threadIdx.x & 31;
    const float* row = x + (size_t)w * Cdim;
    float4 v[5];
    float sum = 0.f, sq = 0.f;
    #pragma unroll
    for (int p = 0; p < 5; p++) {
        v[p] = *reinterpret_cast<const float4*>(row + (lane + 32 * p) * 4);
        sum += v[p].x + v[p].y + v[p].z + v[p].w;
        sq  += v[p].x * v[p].x + v[p].y * v[p].y + v[p].z * v[p].z + v[p].w * v[p].w;
    }
    #pragma unroll
    for (int o = 16; o > 0; o >>= 1) {
        sum += __shfl_xor_sync(0xffffffffu, sum, o);
        sq  += __shfl_xor_sync(0xffffffffu, sq,  o);
    }
    const float mean = sum * (1.f / 640.f);
    const float var  = sq * (1.f / 640.f) - mean * mean;
    const float rstd = rsqrtf(var + 1e-5f);
    float* orow = out + (size_t)w * Cdim;
    #pragma unroll
    for (int p = 0; p < 5; p++) {
        const int off = (lane + 32 * p) * 4;
        const float4 g4 = *reinterpret_cast<const float4*>(g + off);
        const float4 b4 = *reinterpret_cast<const float4*>(b + off);
        float4 o;
        o.x = (v[p].x - mean) * rstd * g4.x + b4.x;
        o.y = (v[p].y - mean) * rstd * g4.y + b4.y;
        o.z = (v[p].z - mean) * rstd * g4.z + b4.z;
        o.w = (v[p].w - mean) * rstd * g4.w + b4.w;
        *reinterpret_cast<float4*>(orow + off) = o;
    }
}

// ---------------- pipelined TF32 GEMM ----------------
// 128x128x32 block tile, 8 warps (2x4), warp tile 64x32.
// 3-stage cp.async ring, ONE __syncthreads per k-tile (prefetch after barrier).
#define ASP 36     // As pitch: frag bank = 4g+tig -> conflict-free
#define BSP 136    // Bs pitch: frag bank = 8tig+g -> conflict-free
#define ASTG (128 * ASP)
#define BSTG (32 * BSP)
#define NSTAGE 3
#define GEMM_SMEM ((NSTAGE * ASTG + NSTAGE * BSTG) * 4)

__global__ __launch_bounds__(256, 2)
void tf32_gemm_kernel(const float* __restrict__ A, const float* __restrict__ B,
                      const float* __restrict__ bias, const float* __restrict__ Res,
                      float* __restrict__ C, int M, int N, int K)
{
    extern __shared__ float smem[];
    float* As = smem;                        // [NSTAGE][128*ASP]
    float* Bs = smem + NSTAGE * ASTG;        // [NSTAGE][32*BSP]
    const int tid  = threadIdx.x;
    const int lane = tid & 31, warp = tid >> 5;
    const int g = lane >> 2, tig = lane & 3;
    const int wm = (warp >> 2) * 64;
    const int wn = (warp & 3) * 32;
    const int row0 = blockIdx.y * 128, col0 = blockIdx.x * 128;

    // staging maps (256 threads)
    const int am = tid >> 1, ak = (tid & 1) * 16;   // A: 4 x cp16
    const int bk = tid >> 3, bn = (tid & 7) * 16;   // B: 4 x cp16
    const bool arow_ok = (row0 + am) < M;
    const float* agp = A + (size_t)(row0 + am) * K + ak;
    const float* bgp = B + (size_t)bk * N + col0 + bn;
    const uint32_t as_d = (uint32_t)__cvta_generic_to_shared(As + am * ASP + ak);
    const uint32_t bs_d = (uint32_t)__cvta_generic_to_shared(Bs + bk * BSP + bn);

    float acc[4][4][4];
    #pragma unroll
    for (int mt = 0; mt < 4; mt++)
        #pragma unroll
        for (int nt = 0; nt < 4; nt++)
            #pragma unroll
            for (int i = 0; i < 4; i++) acc[mt][nt][i] = 0.f;

    const int KT = K >> 5;

    // prologue: stage 0 and 1
    #pragma unroll
    for (int p = 0; p < 2; p++) {
        if (p < KT) {
            const float* ag = agp + p * 32;
            const float* bg = bgp + (size_t)p * 32 * N;
            #pragma unroll
            for (int l = 0; l < 4; l++)
                cp16(as_d + (uint32_t)(p * ASTG * 4) + l * 16, ag + l * 4, arow_ok);
            #pragma unroll
            for (int l = 0; l < 4; l++)
                cp16(bs_d + (uint32_t)(p * BSTG * 4) + l * 16, bg + l * 4, true);
        }
        cp_commit();
    }

    int s = 0, sw = 2;
    for (int kt = 0; kt < KT; kt++) {
        cp_wait<1>();
        __syncthreads();

        // prefetch kt+2 into stage sw (stage last read at iter kt-1 -> safe after barrier)
        if (kt + 2 < KT) {
            const float* ag = agp + (kt + 2) * 32;
            const float* bg = bgp + (size_t)(kt + 2) * 32 * N;
            const uint32_t ad = as_d + (uint32_t)(sw * ASTG * 4);
            const uint32_t bd = bs_d + (uint32_t)(sw * BSTG * 4);
            #pragma unroll
            for (int l = 0; l < 4; l++) cp16(ad + l * 16, ag + l * 4, arow_ok);
            #pragma unroll
            for (int l = 0; l < 4; l++) cp16(bd + l * 16, bg + l * 4, true);
        }
        cp_commit();

        const float* as = As + s * ASTG;
        const float* bs = Bs + s * BSTG;
        #pragma unroll
        for (int ks = 0; ks < 4; ks++) {
            const int kq = ks * 8 + tig;
            uint32_t af[4][4];
            #pragma unroll
            for (int mt = 0; mt < 4; mt++) {
                const int m = wm + mt * 16 + g;
                af[mt][0] = fu(as[m * ASP + kq]);
                af[mt][1] = fu(as[(m + 8) * ASP + kq]);
                af[mt][2] = fu(as[m * ASP + kq + 4]);
                af[mt][3] = fu(as[(m + 8) * ASP + kq + 4]);
            }
            uint32_t bf[4][2];
            #pragma unroll
            for (int nt = 0; nt < 4; nt++) {
                const int n = wn + nt * 8 + g;
                bf[nt][0] = fu(bs[kq * BSP + n]);
                bf[nt][1] = fu(bs[(kq + 4) * BSP + n]);
            }
            #pragma unroll
            for (int mt = 0; mt < 4; mt++)
                #pragma unroll
                for (int nt = 0; nt < 4; nt++)
                    mma_tf32(acc[mt][nt], af[mt], bf[nt]);
        }

        s = (s == NSTAGE - 1) ? 0 : s + 1;
        sw = (sw == NSTAGE - 1) ? 0 : sw + 1;
    }

    // epilogue
    #pragma unroll
    for (int mt = 0; mt < 4; mt++) {
        const int r0 = row0 + wm + mt * 16 + g;
        const int r1 = r0 + 8;
        #pragma unroll
        for (int nt = 0; nt < 4; nt++) {
            const int c = col0 + wn + nt * 8 + 2 * tig;
            float2 v0 = make_float2(acc[mt][nt][0], acc[mt][nt][1]);
            float2 v1 = make_float2(acc[mt][nt][2], acc[mt][nt][3]);
            if (bias) {
                const float2 bb = *reinterpret_cast<const float2*>(bias + c);
                v0.x += bb.x; v0.y += bb.y;
                v1.x += bb.x; v1.y += bb.y;
            }
            if (r0 < M) {
                if (Res) {
                    const float2 rv = *reinterpret_cast<const float2*>(Res + (size_t)r0 * N + c);
                    v0.x += rv.x; v0.y += rv.y;
                }
                *reinterpret_cast<float2*>(C + (size_t)r0 * N + c) = v0;
            }
            if (r1 < M) {
                if (Res) {
                    const float2 rv = *reinterpret_cast<const float2*>(Res + (size_t)r1 * N + c);
                    v1.x += rv.x; v1.y += rv.y;
                }
                *reinterpret_cast<float2*>(C + (size_t)r1 * N + c) = v1;
            }
        }
    }
}

// ---------------- MMA attention scores (strided) ----------------
#define QP 84
__global__ __launch_bounds__(128)
void attn_scores_mma(const float* __restrict__ Q, const float* __restrict__ Kb,
                     float* __restrict__ S, int Tk, int Tpad, int qstr, int kstr)
{
    __shared__ float Qs[64 * QP];
    __shared__ float Ks[64 * QP];
    const int bh = blockIdx.z, b = bh >> 3, n = bh & 7;
    const float* qb = Q + (size_t)b * Sq * qstr + n * HSZ;
    const int i0 = blockIdx.y * 64, j0 = blockIdx.x * 64;
    const int tid = threadIdx.x;
    // K buffer rows: cross-attn (kstr==1280) has Tctx rows; self-attn has Sq rows
    const int kSeq = (kstr == 1280) ? Tctx : Sq;
    const float* kbb = Kb + (size_t)b * kSeq * kstr + n * HSZ;

    for (int e = tid; e < 64 * 20; e += 128) {
        const int r = e / 20, c = (e % 20) * 4;
        const float4 qv = *reinterpret_cast<const float4*>(qb + (size_t)(i0 + r) * qstr + c);
        *reinterpret_cast<float4*>(&Qs[r * QP + c]) = qv;
        float4 kv = make_float4(0.f, 0.f, 0.f, 0.f);
        if (j0 + r < Tk)
            kv = *reinterpret_cast<const float4*>(kbb + (size_t)(j0 + r) * kstr + c);
        *reinterpret_cast<float4*>(&Ks[r * QP + c]) = kv;
    }
    __syncthreads();

    const int lane = tid & 31, warp = tid >> 5;
    const int g = lane >> 2, tig = lane & 3;
    const int wm = (warp >> 1) * 32, wn = (warp & 1) * 32;

    float acc[2][4][4];
    #pragma unroll
    for (int mt = 0; mt < 2; mt++)
        #pragma unroll
        for (int nt = 0; nt < 4; nt++)
            #pragma unroll
            for (int i = 0; i < 4; i++) acc[mt][nt][i] = 0.f;

    #pragma unroll
    for (int ks = 0; ks < 10; ks++) {
        const int kq = ks * 8 + tig;
        uint32_t af[2][4];
        #pragma unroll
        for (int mt = 0; mt < 2; mt++) {
            const int m = wm + mt * 16 + g;
            af[mt][0] = fu(Qs[m * QP + kq]);
            af[mt][1] = fu(Qs[(m + 8) * QP + kq]);
            af[mt][2] = fu(Qs[m * QP + kq + 4]);
            af[mt][3] = fu(Qs[(m + 8) * QP + kq + 4]);
        }
        uint32_t bf[4][2];
        #pragma unroll
        for (int nt = 0; nt < 4; nt++) {
            const int nn = wn + nt * 8 + g;
            bf[nt][0] = fu(Ks[nn * QP + kq]);
            bf[nt][1] = fu(Ks[nn * QP + kq + 4]);
        }
        #pragma unroll
        for (int mt = 0; mt < 2; mt++)
            #pragma unroll
            for (int nt = 0; nt < 4; nt++)
                mma_tf32(acc[mt][nt], af[mt], bf[nt]);
    }

    float* sb = S + (size_t)bh * Sq * Tpad;
    const float scale = 0.11180339887498949f;
    #pragma unroll
    for (int mt = 0; mt < 2; mt++) {
        const int r0 = i0 + wm + mt * 16 + g;
        const int r1 = r0 + 8;
        #pragma unroll
        for (int nt = 0; nt < 4; nt++) {
            const int c = j0 + wn + nt * 8 + 2 * tig;
            if (c < Tk)     { sb[(size_t)r0 * Tpad + c]     = acc[mt][nt][0] * scale;
                              sb[(size_t)r1 * Tpad + c]     = acc[mt][nt][2] * scale; }
            if (c + 1 < Tk) { sb[(size_t)r0 * Tpad + c + 1] = acc[mt][nt][1] * scale;
                              sb[(size_t)r1 * Tpad + c + 1] = acc[mt][nt][3] * scale; }
        }
    }
}

// ---------------- softmax (padded) ----------------
__global__ void softmax_kernel(float* __restrict__ S, int rows, int L, int Lpad)
{
    const int w = (blockIdx.x << 3) + (threadIdx.x >> 5);
    if (w >= rows) return;
    const int lane = threadIdx.x & 31;
    float* row = S + (size_t)w * Lpad;
    float v[32];
    float m = -3.4e38f;
    #pragma unroll
    for (int p = 0; p < 32; p++) {
        const int i = lane + (p << 5);
        v[p] = (i < L) ? row[i] : -3.4e38f;
        m = fmaxf(m, v[p]);
    }
    #pragma unroll
    for (int o = 16; o > 0; o >>= 1) m = fmaxf(m, __shfl_xor_sync(0xffffffffu, m, o));
    float s = 0.f;
    #pragma unroll
    for (int p = 0; p < 32; p++) {
        const int i = lane + (p << 5);
        if (i < L) { v[p] = __expf(v[p] - m); s += v[p]; }
    }
    #pragma unroll
    for (int o = 16; o > 0; o >>= 1) s += __shfl_xor_sync(0xffffffffu, s, o);
    const float inv = 1.f / s;
    #pragma unroll
    for (int p = 0; p < 32; p++) {
        const int i = lane + (p << 5);
        if (i < L) row[i] = v[p] * inv;
        else if (i < Lpad) row[i] = 0.f;
    }
}

// ---------------- MMA attention PV (strided V) ----------------
#define PP 36
#define VP 88
__global__ __launch_bounds__(256)
void attn_pv_mma(const float* __restrict__ P, const float* __restrict__ V,
                 float* __restrict__ O, int Tk, int Tpad, int vstr)
{
    __shared__ float Ps[128 * PP];
    __shared__ float Vs[32 * VP];
    const int bh = blockIdx.z, b = bh >> 3, n = bh & 7;
    const float* pb = P + (size_t)bh * Sq * Tpad;
    const int vSeq = (vstr == 1280) ? Tctx : Sq;
    const float* vb = V + (size_t)b * vSeq * vstr + n * HSZ;
    float* ob = O + (size_t)b * Sq * Cdim + n * HSZ;
    const int i0 = blockIdx.x * 128;
    const int tid = threadIdx.x;
    const int lane = tid & 31, warp = tid >> 5;
    const int g = lane >> 2, tig = lane & 3;
    const int wm = (warp >> 1) * 32, wn = (warp & 1) * 40;

    const int pr = tid >> 1, pc = (tid & 1) * 16;

    float acc[2][5][4];
    #pragma unroll
    for (int mt = 0; mt < 2; mt++)
        #pragma unroll
        for (int nt = 0; nt < 5; nt++)
            #pragma unroll
            for (int i = 0; i < 4; i++) acc[mt][nt][i] = 0.f;

    for (int t0 = 0; t0 < Tpad; t0 += 32) {
        #pragma unroll
        for (int l = 0; l < 4; l++) {
            const float4 pv = *reinterpret_cast<const float4*>(
                pb + (size_t)(i0 + pr) * Tpad + t0 + pc + l * 4);
            *reinterpret_cast<float4*>(&Ps[pr * PP + pc + l * 4]) = pv;
        }
        for (int e = tid; e < 32 * 20; e += 256) {
            const int kr = e / 20, c = (e % 20) * 4;
            float4 vv = make_float4(0.f, 0.f, 0.f, 0.f);
            if (t0 + kr < Tk)
                vv = *reinterpret_cast<const float4*>(vb + (size_t)(t0 + kr) * vstr + c);
            *reinterpret_cast<float4*>(&Vs[kr * VP + c]) = vv;
        }
        __syncthreads();

        #pragma unroll
        for (int ks = 0; ks < 4; ks++) {
            const int kq = ks * 8 + tig;
            uint32_t af[2][4];
            #pragma unroll
            for (int mt = 0; mt < 2; mt++) {
                const int m = wm + mt * 16 + g;
                af[mt][0] = fu(Ps[m * PP + kq]);
                af[mt][1] = fu(Ps[(m + 8) * PP + kq]);
                af[mt][2] = fu(Ps[m * PP + kq + 4]);
                af[mt][3] = fu(Ps[(m + 8) * PP + kq + 4]);
            }
            uint32_t bf[5][2];
            #pragma unroll
            for (int nt = 0; nt < 5; nt++) {
                const int nn = wn + nt * 8 + g;
                bf[nt][0] = fu(Vs[kq * VP + nn]);
                bf[nt][1] = fu(Vs[(kq + 4) * VP + nn]);
            }
            #pragma unroll
            for (int mt = 0; mt < 2; mt++)
                #pragma unroll
                for (int nt = 0; nt < 5; nt++)
                    mma_tf32(acc[mt][nt], af[mt], bf[nt]);
        }
        __syncthreads();
    }

    #pragma unroll
    for (int mt = 0; mt < 2; mt++) {
        const int r0 = i0 + wm + mt * 16 + g;
        const int r1 = r0 + 8;
        #pragma unroll
        for (int nt = 0; nt < 5; nt++) {
            const int c = wn + nt * 8 + 2 * tig;
            *reinterpret_cast<float2*>(ob + (size_t)r0 * Cdim + c) =
                make_float2(acc[mt][nt][0], acc[mt][nt][1]);
            *reinterpret_cast<float2*>(ob + (size_t)r1 * Cdim + c) =
                make_float2(acc[mt][nt][2], acc[mt][nt][3]);
        }
    }
}

// ---------------- GEGLU ----------------
__device__ __forceinline__ float geglu_one(float xh, float g)
{
    const float t = tanhf(g * 0.7978845608f * (1.f + 0.044715f * g * g));
    return xh * 0.5f * g * (1.f + t);
}

__global__ void geglu_kernel(const float* __restrict__ ff, float* __restrict__ out)
{
    const size_t idx = (size_t)blockIdx.x * blockDim.x + threadIdx.x;
    if (idx >= (size_t)Mrows * (FFH / 4)) return;
    const size_t row = idx / (FFH / 4);
    const int c4 = (int)(idx % (FFH / 4));
    const float4 xh = *reinterpret_cast<const float4*>(ff + row * FFD + c4 * 4);
    const float4 gt = *reinterpret_cast<const float4*>(ff + row * FFD + FFH + c4 * 4);
    float4 o;
    o.x = geglu_one(xh.x, gt.x);
    o.y = geglu_one(xh.y, gt.y);
    o.z = geglu_one(xh.z, gt.z);
    o.w = geglu_one(xh.w, gt.w);
    *reinterpret_cast<float4*>(out + row * FFH + c4 * 4) = o;
}

// ---------------- host orchestration ----------------
extern "C" void kernel_launch(void* const* d_in, const int* in_sizes, int n_in,
                              void* d_out, int out_size)
{
    (void)in_sizes; (void)n_in; (void)out_size;
    const float* x     = (const float*)d_in[0];
    const float* ctx   = (const float*)d_in[1];
    const float* gn_g  = (const float*)d_in[2];
    const float* gn_b  = (const float*)d_in[3];
    const float* piw   = (const float*)d_in[4];
    const float* pib   = (const float*)d_in[5];
    const float* ln1g  = (const float*)d_in[6];
    const float* ln1b  = (const float*)d_in[7];
    const float* a1q   = (const float*)d_in[8];
    const float* a1k   = (const float*)d_in[9];
    const float* a1v   = (const float*)d_in[10];
    const float* a1o   = (const float*)d_in[11];
    const float* a1ob  = (const float*)d_in[12];
    const float* ln2g  = (const float*)d_in[13];
    const float* ln2b  = (const float*)d_in[14];
    const float* a2q   = (const float*)d_in[15];
    const float* a2k   = (const float*)d_in[16];
    const float* a2v   = (const float*)d_in[17];
    const float* a2o   = (const float*)d_in[18];
    const float* a2ob  = (const float*)d_in[19];
    const float* ln3g  = (const float*)d_in[20];
    const float* ln3b  = (const float*)d_in[21];
    const float* ff1w  = (const float*)d_in[22];
    const float* ff1b  = (const float*)d_in[23];
    const float* ff2w  = (const float*)d_in[24];
    const float* ff2b  = (const float*)d_in[25];
    const float* prw   = (const float*)d_in[26];
    const float* prb   = (const float*)d_in[27];
    float* out = (float*)d_out;

    float *ln, *y, *q, *at, *t, *sc, *ff, *gg, *qkv, *kv, *wp, *wc;
    cudaGetSymbolAddress((void**)&ln,  g_ln);
    cudaGetSymbolAddress((void**)&y,   g_y);
    cudaGetSymbolAddress((void**)&q,   g_q);
    cudaGetSymbolAddress((void**)&at,  g_at);
    cudaGetSymbolAddress((void**)&t,   g_t);
    cudaGetSymbolAddress((void**)&sc,  g_sc);
    cudaGetSymbolAddress((void**)&ff,  g_ff);
    cudaGetSymbolAddress((void**)&gg,  g_gg);
    cudaGetSymbolAddress((void**)&qkv, g_qkv);
    cudaGetSymbolAddress((void**)&kv,  g_kv);
    cudaGetSymbolAddress((void**)&wp,  g_wp);
    cudaGetSymbolAddress((void**)&wc,  g_wc);

    cudaFuncSetAttribute(tf32_gemm_kernel,
                         cudaFuncAttributeMaxDynamicSharedMemorySize, GEMM_SMEM);

    const dim3 gemm640(Cdim / 128, Mrows / 128);           // (5, 64)
    const dim3 gemmQKV(1920 / 128, Mrows / 128);           // (15, 64)
    const dim3 gemmKV(1280 / 128, (MCTX + 127) / 128);     // (10, 5)
    const dim3 gemmFF(FFD / 128, Mrows / 128);             // (40, 64)

    // pack fused weights (deterministic, same every call)
    pack3_kernel<<<256, 256>>>(a1q, a1k, a1v, wp, Cdim);
    pack2_kernel<<<256, 256>>>(a2k, a2v, wc, CTXD);

    // y = proj_in(group_norm(x))
    groupnorm_kernel<<<Bn * 32, 256>>>(x, gn_g, gn_b, ln);
    tf32_gemm_kernel<<<gemm640, 256, GEMM_SMEM>>>(ln, piw, pib, nullptr, y, Mrows, Cdim, Cdim);

    // self attention (fused QKV: q=col0, k=col640, v=col1280, row stride 1920)
    layernorm_kernel<<<Mrows / 8, 256>>>(y, ln1g, ln1b, ln, Mrows);
    tf32_gemm_kernel<<<gemmQKV, 256, GEMM_SMEM>>>(ln, wp, nullptr, nullptr, qkv, Mrows, 1920, Cdim);
    attn_scores_mma<<<dim3(16, 16, 64), 128>>>(qkv, qkv + 640, sc, Sq, Sq, 1920, 1920);
    softmax_kernel<<<(64 * Sq) / 8, 256>>>(sc, 64 * Sq, Sq, Sq);
    attn_pv_mma<<<dim3(8, 1, 64), 256>>>(sc, qkv + 1280, at, Sq, Sq, 1920);
    tf32_gemm_kernel<<<gemm640, 256, GEMM_SMEM>>>(at, a1o, a1ob, y, t, Mrows, Cdim, Cdim);

    // cross attention (fused KV: k=col0, v=col640, row stride 1280)
    layernorm_kernel<<<Mrows / 8, 256>>>(t, ln2g, ln2b, ln, Mrows);
    tf32_gemm_kernel<<<gemmKV, 256, GEMM_SMEM>>>(ctx, wc, nullptr, nullptr, kv, MCTX, 1280, CTXD);
    tf32_gemm_kernel<<<gemm640, 256, GEMM_SMEM>>>(ln, a2q, nullptr, nullptr, q, Mrows, Cdim, Cdim);
    attn_scores_mma<<<dim3(2, 16, 64), 128>>>(q, kv, sc, Tctx, TPAD, Cdim, 1280);
    softmax_kernel<<<(64 * Sq) / 8, 256>>>(sc, 64 * Sq, Tctx, TPAD);
    attn_pv_mma<<<dim3(8, 1, 64), 256>>>(sc, kv + 640, at, Tctx, TPAD, 1280);
    tf32_gemm_kernel<<<gemm640, 256, GEMM_SMEM>>>(at, a2o, a2ob, t, t, Mrows, Cdim, Cdim);

    // GEGLU feed-forward
    layernorm_kernel<<<Mrows / 8, 256>>>(t, ln3g, ln3b, ln, Mrows);
    tf32_gemm_kernel<<<gemmFF, 256, GEMM_SMEM>>>(ln, ff1w, ff1b, nullptr, ff, Mrows, FFD, Cdim);
    geglu_kernel<<<(Mrows * (FFH / 4)) / 256, 256>>>(ff, gg);
    tf32_gemm_kernel<<<gemm640, 256, GEMM_SMEM>>>(gg, ff2w, ff2b, t, t, Mrows, Cdim, FFH);

    // proj_out + input residual
    tf32_gemm_kernel<<<gemm640, 256, GEMM_SMEM>>>(t, prw, prb, x, out, Mrows, Cdim, Cdim);
}

// round 11
// speedup vs baseline: 1.6454x; 1.4399x over previous
#include <cuda_runtime.h>
#include <cuda_fp16.h>
#include <math.h>
#include <stdint.h>

// ---------------- problem dims ----------------
#define Bn    8
#define Sq    1024
#define Cdim  640
#define Tctx  77
#define TPAD  96
#define CTXD  768
#define NHEAD 8
#define HSZ   80
#define FFD   5120
#define FFH   2560
#define Mrows (Bn * Sq)      // 8192
#define MCTX  (Bn * Tctx)    // 616

// ---------------- scratch ----------------
__device__ float  g_y   [(size_t)Mrows * Cdim];
__device__ float  g_t   [(size_t)Mrows * Cdim];
__device__ float  g_sc  [(size_t)64 * 1024 * 1024];
__device__ __half g_p16 [(size_t)64 * 1024 * 1024];
__device__ __half g_ln16[(size_t)Mrows * Cdim];
__device__ __half g_q16 [(size_t)Mrows * Cdim];
__device__ __half g_at16[(size_t)Mrows * Cdim];
__device__ __half g_t16 [(size_t)Mrows * Cdim];
__device__ __half g_ctx16[(size_t)MCTX * CTXD];
__device__ __half g_qkv16[(size_t)Mrows * 1920];
__device__ __half g_kv16 [(size_t)MCTX * 1280];
__device__ __half g_ff16 [(size_t)Mrows * FFD];
__device__ __half g_gg16 [(size_t)Mrows * FFH];
// transposed fp16 weights [N][K]
__device__ __half g_piwT[(size_t)Cdim * Cdim];
__device__ __half g_wpT [(size_t)1920 * Cdim];
__device__ __half g_a2qT[(size_t)Cdim * Cdim];
__device__ __half g_wcT [(size_t)1280 * CTXD];
__device__ __half g_a1oT[(size_t)Cdim * Cdim];
__device__ __half g_a2oT[(size_t)Cdim * Cdim];
__device__ __half g_ff1T[(size_t)FFD * Cdim];
__device__ __half g_ff2T[(size_t)Cdim * FFH];
__device__ __half g_prwT[(size_t)Cdim * Cdim];

// ---------------- helpers ----------------
__device__ __forceinline__ void mma_f16(float* c, const uint32_t* a, const uint32_t* b)
{
    asm volatile(
        "mma.sync.aligned.m16n8k16.row.col.f32.f16.f16.f32 "
        "{%0,%1,%2,%3}, {%4,%5,%6,%7}, {%8,%9}, {%0,%1,%2,%3};"
        : "+f"(c[0]), "+f"(c[1]), "+f"(c[2]), "+f"(c[3])
        : "r"(a[0]), "r"(a[1]), "r"(a[2]), "r"(a[3]), "r"(b[0]), "r"(b[1]));
}

__device__ __forceinline__ void cp16(uint32_t dst, const void* src, bool pred)
{
    const int sz = pred ? 16 : 0;
    asm volatile("cp.async.cg.shared.global [%0], [%1], 16, %2;\n"
                 :: "r"(dst), "l"(src), "r"(sz));
}
__device__ __forceinline__ void cp_commit() { asm volatile("cp.async.commit_group;\n"); }
template <int N>
__device__ __forceinline__ void cp_wait() { asm volatile("cp.async.wait_group %0;\n" :: "n"(N)); }

// ---------------- weight transpose+convert: in fp32 [K][N] -> out fp16 [N][K] ----------------
__global__ void wT_kernel(const float* __restrict__ in, __half* __restrict__ out, int K, int N)
{
    __shared__ float t[32][33];
    const int kt = blockIdx.y * 32, nt = blockIdx.x * 32;
    const int tx = threadIdx.x & 31, ty = threadIdx.x >> 5;   // 32x8
    #pragma unroll
    for (int r = ty; r < 32; r += 8)
        t[r][tx] = in[(size_t)(kt + r) * N + nt + tx];
    __syncthreads();
    #pragma unroll
    for (int r = ty; r < 32; r += 8)
        out[(size_t)(nt + r) * K + kt + tx] = __float2half(t[tx][r]);
}

// ---------------- fp32 -> fp16 elementwise (count multiple of 4) ----------------
__global__ void f2h_kernel(const float* __restrict__ in, __half* __restrict__ out, int n4)
{
    const int i = blockIdx.x * blockDim.x + threadIdx.x;
    if (i >= n4) return;
    const float4 v = *reinterpret_cast<const float4*>(in + (size_t)i * 4);
    __half2 h0 = __floats2half2_rn(v.x, v.y);
    __half2 h1 = __floats2half2_rn(v.z, v.w);
    uint2 u; u.x = *reinterpret_cast<uint32_t*>(&h0); u.y = *reinterpret_cast<uint32_t*>(&h1);
    *reinterpret_cast<uint2*>(out + (size_t)i * 4) = u;
}

// ---------------- GroupNorm (fp32 in, fp16 out) ----------------
__global__ void groupnorm_kernel(const float* __restrict__ x,
                                 const float* __restrict__ gamma,
                                 const float* __restrict__ beta,
                                 __half* __restrict__ out)
{
    const int b = blockIdx.x >> 5;
    const int g = blockIdx.x & 31;
    const float* base = x + (size_t)b * Sq * Cdim + g * 20;
    float sum = 0.f, sq = 0.f;
    for (int idx = threadIdx.x; idx < Sq * 20; idx += 256) {
        int hw = idx / 20, c = idx % 20;
        float v = base[(size_t)hw * Cdim + c];
        sum += v; sq += v * v;
    }
    #pragma unroll
    for (int o = 16; o > 0; o >>= 1) {
        sum += __shfl_xor_sync(0xffffffffu, sum, o);
        sq  += __shfl_xor_sync(0xffffffffu, sq,  o);
    }
    __shared__ float s1[8], s2[8];
    const int wid = threadIdx.x >> 5, lane = threadIdx.x & 31;
    if (lane == 0) { s1[wid] = sum; s2[wid] = sq; }
    __syncthreads();
    float tot = 0.f, totq = 0.f;
    #pragma unroll
    for (int i = 0; i < 8; i++) { tot += s1[i]; totq += s2[i]; }
    const float mean = tot * (1.f / 20480.f);
    const float var  = totq * (1.f / 20480.f) - mean * mean;
    const float rstd = rsqrtf(var + 1e-5f);
    __half* ob = out + (size_t)b * Sq * Cdim + g * 20;
    for (int idx = threadIdx.x; idx < Sq * 20; idx += 256) {
        int hw = idx / 20, c = idx % 20;
        float v = base[(size_t)hw * Cdim + c];
        ob[(size_t)hw * Cdim + c] =
            __float2half((v - mean) * rstd * gamma[g * 20 + c] + beta[g * 20 + c]);
    }
}

// ---------------- LayerNorm (fp32 in, fp16 out) ----------------
__global__ void layernorm_kernel(const float* __restrict__ x,
                                 const float* __restrict__ g,
                                 const float* __restrict__ b,
                                 __half* __restrict__ out, int rows)
{
    const int w = (blockIdx.x << 3) + (threadIdx.x >> 5);
    if (w >= rows) return;
    const int lane = threadIdx.x & 31;
    const float* row = x + (size_t)w * Cdim;
    float4 v[5];
    float sum = 0.f, sq = 0.f;
    #pragma unroll
    for (int p = 0; p < 5; p++) {
        v[p] = *reinterpret_cast<const float4*>(row + (lane + 32 * p) * 4);
        sum += v[p].x + v[p].y + v[p].z + v[p].w;
        sq  += v[p].x * v[p].x + v[p].y * v[p].y + v[p].z * v[p].z + v[p].w * v[p].w;
    }
    #pragma unroll
    for (int o = 16; o > 0; o >>= 1) {
        sum += __shfl_xor_sync(0xffffffffu, sum, o);
        sq  += __shfl_xor_sync(0xffffffffu, sq,  o);
    }
    const float mean = sum * (1.f / 640.f);
    const float var  = sq * (1.f / 640.f) - mean * mean;
    const float rstd = rsqrtf(var + 1e-5f);
    __half* orow = out + (size_t)w * Cdim;
    #pragma unroll
    for (int p = 0; p < 5; p++) {
        const int off = (lane + 32 * p) * 4;
        const float4 g4 = *reinterpret_cast<const float4*>(g + off);
        const float4 b4 = *reinterpret_cast<const float4*>(b + off);
        __half2 h0 = __floats2half2_rn((v[p].x - mean) * rstd * g4.x + b4.x,
                                       (v[p].y - mean) * rstd * g4.y + b4.y);
        __half2 h1 = __floats2half2_rn((v[p].z - mean) * rstd * g4.z + b4.z,
                                       (v[p].w - mean) * rstd * g4.w + b4.w);
        uint2 u; u.x = *reinterpret_cast<uint32_t*>(&h0); u.y = *reinterpret_cast<uint32_t*>(&h1);
        *reinterpret_cast<uint2*>(orow + off) = u;
    }
}

// ---------------- pipelined FP16 GEMM ----------------
// C = A[M,K](fp16) @ Bt[N,K](fp16)^T; 128x128x32 tile, 8 warps (2x4), warp 64x32.
// 3-stage cp.async ring, one __syncthreads per k-tile.
#define HP   40                     // smem pitch in halfs (frag bank = g*20+tig: permutation)
#define HP2  20                     // pitch in uint32
#define STGH (128 * HP)             // halfs per stage (A or B)
#define STGB (STGH * 2)             // bytes per stage
#define NSTAGE 3
#define GEMM_SMEM (NSTAGE * 2 * STGB)

__global__ __launch_bounds__(256, 2)
void hgemm_kernel(const __half* __restrict__ A, const __half* __restrict__ Bt,
                  const float* __restrict__ bias, const float* __restrict__ Res,
                  float* __restrict__ C32, __half* __restrict__ C16,
                  int M, int N, int K)
{
    extern __shared__ __half smem[];
    __half* As = smem;                       // [NSTAGE][128*HP]
    __half* Bs = smem + NSTAGE * STGH;       // [NSTAGE][128*HP]
    const int tid  = threadIdx.x;
    const int lane = tid & 31, warp = tid >> 5;
    const int g = lane >> 2, tig = lane & 3;
    const int wm = (warp >> 2) * 64;
    const int wn = (warp & 3) * 32;
    const int row0 = blockIdx.y * 128, col0 = blockIdx.x * 128;

    // staging: 2 threads per 128-row tile row, 16 halfs (2 x cp16) each
    const int srow = tid >> 1, soff = (tid & 1) * 16;
    const bool arow_ok = (row0 + srow) < M;
    const __half* agp = A  + (size_t)(row0 + srow) * K + soff;
    const __half* bgp = Bt + (size_t)(col0 + srow) * K + soff;
    const uint32_t as_d = (uint32_t)__cvta_generic_to_shared(As + srow * HP + soff);
    const uint32_t bs_d = (uint32_t)__cvta_generic_to_shared(Bs + srow * HP + soff);

    float acc[4][4][4];
    #pragma unroll
    for (int mt = 0; mt < 4; mt++)
        #pragma unroll
        for (int nt = 0; nt < 4; nt++)
            #pragma unroll
            for (int i = 0; i < 4; i++) acc[mt][nt][i] = 0.f;

    const int KT = K >> 5;   // 32 halfs per tile

    #pragma unroll
    for (int p = 0; p < 2; p++) {
        if (p < KT) {
            const __half* ag = agp + p * 32;
            const __half* bg = bgp + p * 32;
            #pragma unroll
            for (int l = 0; l < 2; l++) cp16(as_d + (uint32_t)(p * STGB) + l * 16, ag + l * 8, arow_ok);
            #pragma unroll
            for (int l = 0; l < 2; l++) cp16(bs_d + (uint32_t)(p * STGB) + l * 16, bg + l * 8, true);
        }
        cp_commit();
    }

    int s = 0, sw = 2;
    for (int kt = 0; kt < KT; kt++) {
        cp_wait<1>();
        __syncthreads();

        if (kt + 2 < KT) {
            const __half* ag = agp + (kt + 2) * 32;
            const __half* bg = bgp + (kt + 2) * 32;
            const uint32_t ad = as_d + (uint32_t)(sw * STGB);
            const uint32_t bd = bs_d + (uint32_t)(sw * STGB);
            #pragma unroll
            for (int l = 0; l < 2; l++) cp16(ad + l * 16, ag + l * 8, arow_ok);
            #pragma unroll
            for (int l = 0; l < 2; l++) cp16(bd + l * 16, bg + l * 8, true);
        }
        cp_commit();

        const uint32_t* as32 = reinterpret_cast<const uint32_t*>(As + s * STGH);
        const uint32_t* bs32 = reinterpret_cast<const uint32_t*>(Bs + s * STGH);
        #pragma unroll
        for (int ks = 0; ks < 2; ks++) {
            const int k2 = ks * 8 + tig;          // uint32 units
            uint32_t af[4][4];
            #pragma unroll
            for (int mt = 0; mt < 4; mt++) {
                const int m = wm + mt * 16 + g;
                af[mt][0] = as32[m * HP2 + k2];
                af[mt][1] = as32[(m + 8) * HP2 + k2];
                af[mt][2] = as32[m * HP2 + k2 + 4];
                af[mt][3] = as32[(m + 8) * HP2 + k2 + 4];
            }
            uint32_t bf[4][2];
            #pragma unroll
            for (int nt = 0; nt < 4; nt++) {
                const int n = wn + nt * 8 + g;
                bf[nt][0] = bs32[n * HP2 + k2];
                bf[nt][1] = bs32[n * HP2 + k2 + 4];
            }
            #pragma unroll
            for (int mt = 0; mt < 4; mt++)
                #pragma unroll
                for (int nt = 0; nt < 4; nt++)
                    mma_f16(acc[mt][nt], af[mt], bf[nt]);
        }

        s = (s == NSTAGE - 1) ? 0 : s + 1;
        sw = (sw == NSTAGE - 1) ? 0 : sw + 1;
    }

    // epilogue
    #pragma unroll
    for (int mt = 0; mt < 4; mt++) {
        const int r0 = row0 + wm + mt * 16 + g;
        const int r1 = r0 + 8;
        #pragma unroll
        for (int nt = 0; nt < 4; nt++) {
            const int c = col0 + wn + nt * 8 + 2 * tig;
            float2 v0 = make_float2(acc[mt][nt][0], acc[mt][nt][1]);
            float2 v1 = make_float2(acc[mt][nt][2], acc[mt][nt][3]);
            if (bias) {
                const float2 bb = *reinterpret_cast<const float2*>(bias + c);
                v0.x += bb.x; v0.y += bb.y;
                v1.x += bb.x; v1.y += bb.y;
            }
            if (r0 < M) {
                if (Res) {
                    const float2 rv = *reinterpret_cast<const float2*>(Res + (size_t)r0 * N + c);
                    v0.x += rv.x; v0.y += rv.y;
                }
                if (C32) *reinterpret_cast<float2*>(C32 + (size_t)r0 * N + c) = v0;
                if (C16) {
                    __half2 h = __floats2half2_rn(v0.x, v0.y);
                    *reinterpret_cast<__half2*>(C16 + (size_t)r0 * N + c) = h;
                }
            }
            if (r1 < M) {
                if (Res) {
                    const float2 rv = *reinterpret_cast<const float2*>(Res + (size_t)r1 * N + c);
                    v1.x += rv.x; v1.y += rv.y;
                }
                if (C32) *reinterpret_cast<float2*>(C32 + (size_t)r1 * N + c) = v1;
                if (C16) {
                    __half2 h = __floats2half2_rn(v1.x, v1.y);
                    *reinterpret_cast<__half2*>(C16 + (size_t)r1 * N + c) = h;
                }
            }
        }
    }
}

// ---------------- FP16 attention scores ----------------
#define QHP  88    // pitch halfs; frag bank = g*12+tig: permutation
#define QHP2 44
__global__ __launch_bounds__(128)
void attn_scores_h(const __half* __restrict__ Q, const __half* __restrict__ Kb,
                   float* __restrict__ S, int Tk, int Tpad, int qstr, int kstr)
{
    __shared__ __half Qs[64 * QHP];
    __shared__ __half Ks[64 * QHP];
    const int bh = blockIdx.z, b = bh >> 3, n = bh & 7;
    const __half* qb = Q + (size_t)b * Sq * qstr + n * HSZ;
    const int kSeq = (kstr == 1280) ? Tctx : Sq;
    const __half* kbb = Kb + (size_t)b * kSeq * kstr + n * HSZ;
    const int i0 = blockIdx.y * 64, j0 = blockIdx.x * 64;
    const int tid = threadIdx.x;

    for (int e = tid; e < 64 * 10; e += 128) {
        const int r = e / 10, c8 = (e % 10) * 8;
        const uint4 qv = *reinterpret_cast<const uint4*>(qb + (size_t)(i0 + r) * qstr + c8);
        *reinterpret_cast<uint4*>(&Qs[r * QHP + c8]) = qv;
        uint4 kv = make_uint4(0u, 0u, 0u, 0u);
        if (j0 + r < Tk)
            kv = *reinterpret_cast<const uint4*>(kbb + (size_t)(j0 + r) * kstr + c8);
        *reinterpret_cast<uint4*>(&Ks[r * QHP + c8]) = kv;
    }
    __syncthreads();

    const int lane = tid & 31, warp = tid >> 5;
    const int g = lane >> 2, tig = lane & 3;
    const int wm = (warp >> 1) * 32, wn = (warp & 1) * 32;
    const uint32_t* qs32 = reinterpret_cast<const uint32_t*>(Qs);
    const uint32_t* ks32 = reinterpret_cast<const uint32_t*>(Ks);

    float acc[2][4][4];
    #pragma unroll
    for (int mt = 0; mt < 2; mt++)
        #pragma unroll
        for (int nt = 0; nt < 4; nt++)
            #pragma unroll
            for (int i = 0; i < 4; i++) acc[mt][nt][i] = 0.f;

    #pragma unroll
    for (int ks = 0; ks < 5; ks++) {           // K = 80 = 5 x k16
        const int k2 = ks * 8 + tig;
        uint32_t af[2][4];
        #pragma unroll
        for (int mt = 0; mt < 2; mt++) {
            const int m = wm + mt * 16 + g;
            af[mt][0] = qs32[m * QHP2 + k2];
            af[mt][1] = qs32[(m + 8) * QHP2 + k2];
            af[mt][2] = qs32[m * QHP2 + k2 + 4];
            af[mt][3] = qs32[(m + 8) * QHP2 + k2 + 4];
        }
        uint32_t bf[4][2];
        #pragma unroll
        for (int nt = 0; nt < 4; nt++) {
            const int nn = wn + nt * 8 + g;
            bf[nt][0] = ks32[nn * QHP2 + k2];
            bf[nt][1] = ks32[nn * QHP2 + k2 + 4];
        }
        #pragma unroll
        for (int mt = 0; mt < 2; mt++)
            #pragma unroll
            for (int nt = 0; nt < 4; nt++)
                mma_f16(acc[mt][nt], af[mt], bf[nt]);
    }

    float* sb = S + (size_t)bh * Sq * Tpad;
    const float scale = 0.11180339887498949f;
    #pragma unroll
    for (int mt = 0; mt < 2; mt++) {
        const int r0 = i0 + wm + mt * 16 + g;
        const int r1 = r0 + 8;
        #pragma unroll
        for (int nt = 0; nt < 4; nt++) {
            const int c = j0 + wn + nt * 8 + 2 * tig;
            if (c < Tk)     { sb[(size_t)r0 * Tpad + c]     = acc[mt][nt][0] * scale;
                              sb[(size_t)r1 * Tpad + c]     = acc[mt][nt][2] * scale; }
            if (c + 1 < Tk) { sb[(size_t)r0 * Tpad + c + 1] = acc[mt][nt][1] * scale;
                              sb[(size_t)r1 * Tpad + c + 1] = acc[mt][nt][3] * scale; }
        }
    }
}

// ---------------- softmax: fp32 scores -> fp16 probs (padded w/ zeros) ----------------
__global__ void softmax_h(const float* __restrict__ S, __half* __restrict__ P,
                          int rows, int L, int Lpad)
{
    const int w = (blockIdx.x << 3) + (threadIdx.x >> 5);
    if (w >= rows) return;
    const int lane = threadIdx.x & 31;
    const float* row = S + (size_t)w * Lpad;
    __half* prow = P + (size_t)w * Lpad;
    float v[32];
    float m = -3.4e38f;
    #pragma unroll
    for (int p = 0; p < 32; p++) {
        const int i = lane + (p << 5);
        v[p] = (i < L) ? row[i] : -3.4e38f;
        m = fmaxf(m, v[p]);
    }
    #pragma unroll
    for (int o = 16; o > 0; o >>= 1) m = fmaxf(m, __shfl_xor_sync(0xffffffffu, m, o));
    float s = 0.f;
    #pragma unroll
    for (int p = 0; p < 32; p++) {
        const int i = lane + (p << 5);
        if (i < L) { v[p] = __expf(v[p] - m); s += v[p]; }
    }
    #pragma unroll
    for (int o = 16; o > 0; o >>= 1) s += __shfl_xor_sync(0xffffffffu, s, o);
    const float inv = 1.f / s;
    #pragma unroll
    for (int p = 0; p < 32; p++) {
        const int i = lane + (p << 5);
        if (i < L) prow[i] = __float2half(v[p] * inv);
        else if (i < Lpad) prow[i] = __float2half(0.f);
    }
}

// ---------------- FP16 attention PV ----------------
// block 128 rows x 80 cols, 8 warps (4x2), warp 32x40. V transposed in smem.
__global__ __launch_bounds__(256)
void attn_pv_h(const __half* __restrict__ P, const __half* __restrict__ V,
               __half* __restrict__ O, int Tk, int Tpad, int vstr)
{
    __shared__ __half Ps[128 * HP];
    __shared__ __half Vs[80 * HP];       // transposed: Vs[c][t]
    const int bh = blockIdx.z, b = bh >> 3, n = bh & 7;
    const __half* pb = P + (size_t)bh * Sq * Tpad;
    const int vSeq = (vstr == 1280) ? Tctx : Sq;
    const __half* vb = V + (size_t)b * vSeq * vstr + n * HSZ;
    __half* ob = O + (size_t)b * Sq * Cdim + n * HSZ;
    const int i0 = blockIdx.x * 128;
    const int tid = threadIdx.x;
    const int lane = tid & 31, warp = tid >> 5;
    const int g = lane >> 2, tig = lane & 3;
    const int wm = (warp >> 1) * 32, wn = (warp & 1) * 40;
    const int pr = tid >> 1, po = (tid & 1) * 16;

    float acc[2][5][4];
    #pragma unroll
    for (int mt = 0; mt < 2; mt++)
        #pragma unroll
        for (int nt = 0; nt < 5; nt++)
            #pragma unroll
            for (int i = 0; i < 4; i++) acc[mt][nt][i] = 0.f;

    const uint32_t* ps32 = reinterpret_cast<const uint32_t*>(Ps);
    const uint32_t* vs32 = reinterpret_cast<const uint32_t*>(Vs);

    for (int t0 = 0; t0 < Tpad; t0 += 32) {
        #pragma unroll
        for (int l = 0; l < 2; l++) {
            const uint4 pv = *reinterpret_cast<const uint4*>(
                pb + (size_t)(i0 + pr) * Tpad + t0 + po + l * 8);
            *reinterpret_cast<uint4*>(&Ps[pr * HP + po + l * 8]) = pv;
        }
        for (int e = tid; e < 80 * 32; e += 256) {
            const int tt = e / 80, c = e % 80;
            Vs[c * HP + tt] = (t0 + tt < Tk) ? vb[(size_t)(t0 + tt) * vstr + c]
                                             : __float2half(0.f);
        }
        __syncthreads();

        #pragma unroll
        for (int ks = 0; ks < 2; ks++) {
            const int k2 = ks * 8 + tig;
            uint32_t af[2][4];
            #pragma unroll
            for (int mt = 0; mt < 2; mt++) {
                const int m = wm + mt * 16 + g;
                af[mt][0] = ps32[m * HP2 + k2];
                af[mt][1] = ps32[(m + 8) * HP2 + k2];
                af[mt][2] = ps32[m * HP2 + k2 + 4];
                af[mt][3] = ps32[(m + 8) * HP2 + k2 + 4];
            }
            uint32_t bf[5][2];
            #pragma unroll
            for (int nt = 0; nt < 5; nt++) {
                const int nn = wn + nt * 8 + g;
                bf[nt][0] = vs32[nn * HP2 + k2];
                bf[nt][1] = vs32[nn * HP2 + k2 + 4];
            }
            #pragma unroll
            for (int mt = 0; mt < 2; mt++)
                #pragma unroll
                for (int nt = 0; nt < 5; nt++)
                    mma_f16(acc[mt][nt], af[mt], bf[nt]);
        }
        __syncthreads();
    }

    #pragma unroll
    for (int mt = 0; mt < 2; mt++) {
        const int r0 = i0 + wm + mt * 16 + g;
        const int r1 = r0 + 8;
        #pragma unroll
        for (int nt = 0; nt < 5; nt++) {
            const int c = wn + nt * 8 + 2 * tig;
            *reinterpret_cast<__half2*>(ob + (size_t)r0 * Cdim + c) =
                __floats2half2_rn(acc[mt][nt][0], acc[mt][nt][1]);
            *reinterpret_cast<__half2*>(ob + (size_t)r1 * Cdim + c) =
                __floats2half2_rn(acc[mt][nt][2], acc[mt][nt][3]);
        }
    }
}

// ---------------- GEGLU (fp16 in/out, fp32 math) ----------------
__device__ __forceinline__ float geglu_one(float xh, float g)
{
    const float t = tanhf(g * 0.7978845608f * (1.f + 0.044715f * g * g));
    return xh * 0.5f * g * (1.f + t);
}

__global__ void geglu_h(const __half* __restrict__ ff, __half* __restrict__ out)
{
    const size_t idx = (size_t)blockIdx.x * blockDim.x + threadIdx.x;  // 8-half chunks
    if (idx >= (size_t)Mrows * (FFH / 8)) return;
    const size_t row = idx / (FFH / 8);
    const int c8 = (int)(idx % (FFH / 8)) * 8;
    const uint4 xh4 = *reinterpret_cast<const uint4*>(ff + row * FFD + c8);
    const uint4 gt4 = *reinterpret_cast<const uint4*>(ff + row * FFD + FFH + c8);
    const __half2* xh = reinterpret_cast<const __half2*>(&xh4);
    const __half2* gt = reinterpret_cast<const __half2*>(&gt4);
    uint4 o4;
    __half2* oh = reinterpret_cast<__half2*>(&o4);
    #pragma unroll
    for (int i = 0; i < 4; i++) {
        const float2 xf = __half22float2(xh[i]);
        const float2 gf = __half22float2(gt[i]);
        oh[i] = __floats2half2_rn(geglu_one(xf.x, gf.x), geglu_one(xf.y, gf.y));
    }
    *reinterpret_cast<uint4*>(out + row * FFH + c8) = o4;
}

// ---------------- host orchestration ----------------
extern "C" void kernel_launch(void* const* d_in, const int* in_sizes, int n_in,
                              void* d_out, int out_size)
{
    (void)in_sizes; (void)n_in; (void)out_size;
    const float* x     = (const float*)d_in[0];
    const float* ctx   = (const float*)d_in[1];
    const float* gn_g  = (const float*)d_in[2];
    const float* gn_b  = (const float*)d_in[3];
    const float* piw   = (const float*)d_in[4];
    const float* pib   = (const float*)d_in[5];
    const float* ln1g  = (const float*)d_in[6];
    const float* ln1b  = (const float*)d_in[7];
    const float* a1q   = (const float*)d_in[8];
    const float* a1k   = (const float*)d_in[9];
    const float* a1v   = (const float*)d_in[10];
    const float* a1o   = (const float*)d_in[11];
    const float* a1ob  = (const float*)d_in[12];
    const float* ln2g  = (const float*)d_in[13];
    const float* ln2b  = (const float*)d_in[14];
    const float* a2q   = (const float*)d_in[15];
    const float* a2k   = (const float*)d_in[16];
    const float* a2v   = (const float*)d_in[17];
    const float* a2o   = (const float*)d_in[18];
    const float* a2ob  = (const float*)d_in[19];
    const float* ln3g  = (const float*)d_in[20];
    const float* ln3b  = (const float*)d_in[21];
    const float* ff1w  = (const float*)d_in[22];
    const float* ff1b  = (const float*)d_in[23];
    const float* ff2w  = (const float*)d_in[24];
    const float* ff2b  = (const float*)d_in[25];
    const float* prw   = (const float*)d_in[26];
    const float* prb   = (const float*)d_in[27];
    float* out = (float*)d_out;

    float *y, *t, *sc;
    __half *p16, *ln16, *q16, *at16, *t16, *ctx16, *qkv16, *kv16, *ff16, *gg16;
    __half *piwT, *wpT, *a2qT, *wcT, *a1oT, *a2oT, *ff1T, *ff2T, *prwT;
    cudaGetSymbolAddress((void**)&y,    g_y);
    cudaGetSymbolAddress((void**)&t,    g_t);
    cudaGetSymbolAddress((void**)&sc,   g_sc);
    cudaGetSymbolAddress((void**)&p16,  g_p16);
    cudaGetSymbolAddress((void**)&ln16, g_ln16);
    cudaGetSymbolAddress((void**)&q16,  g_q16);
    cudaGetSymbolAddress((void**)&at16, g_at16);
    cudaGetSymbolAddress((void**)&t16,  g_t16);
    cudaGetSymbolAddress((void**)&ctx16,g_ctx16);
    cudaGetSymbolAddress((void**)&qkv16,g_qkv16);
    cudaGetSymbolAddress((void**)&kv16, g_kv16);
    cudaGetSymbolAddress((void**)&ff16, g_ff16);
    cudaGetSymbolAddress((void**)&gg16, g_gg16);
    cudaGetSymbolAddress((void**)&piwT, g_piwT);
    cudaGetSymbolAddress((void**)&wpT,  g_wpT);
    cudaGetSymbolAddress((void**)&a2qT, g_a2qT);
    cudaGetSymbolAddress((void**)&wcT,  g_wcT);
    cudaGetSymbolAddress((void**)&a1oT, g_a1oT);
    cudaGetSymbolAddress((void**)&a2oT, g_a2oT);
    cudaGetSymbolAddress((void**)&ff1T, g_ff1T);
    cudaGetSymbolAddress((void**)&ff2T, g_ff2T);
    cudaGetSymbolAddress((void**)&prwT, g_prwT);

    cudaFuncSetAttribute(hgemm_kernel,
                         cudaFuncAttributeMaxDynamicSharedMemorySize, GEMM_SMEM);

    // ---- weight transpose+convert (deterministic each call) ----
    wT_kernel<<<dim3(Cdim/32, Cdim/32), 256>>>(piw,  piwT, Cdim, Cdim);
    wT_kernel<<<dim3(Cdim/32, Cdim/32), 256>>>(a1q,  wpT,                         Cdim, Cdim);
    wT_kernel<<<dim3(Cdim/32, Cdim/32), 256>>>(a1k,  wpT + (size_t)640 * Cdim,    Cdim, Cdim);
    wT_kernel<<<dim3(Cdim/32, Cdim/32), 256>>>(a1v,  wpT + (size_t)1280 * Cdim,   Cdim, Cdim);
    wT_kernel<<<dim3(Cdim/32, Cdim/32), 256>>>(a2q,  a2qT, Cdim, Cdim);
    wT_kernel<<<dim3(Cdim/32, CTXD/32), 256>>>(a2k,  wcT,                         CTXD, Cdim);
    wT_kernel<<<dim3(Cdim/32, CTXD/32), 256>>>(a2v,  wcT + (size_t)640 * CTXD,    CTXD, Cdim);
    wT_kernel<<<dim3(Cdim/32, Cdim/32), 256>>>(a1o,  a1oT, Cdim, Cdim);
    wT_kernel<<<dim3(Cdim/32, Cdim/32), 256>>>(a2o,  a2oT, Cdim, Cdim);
    wT_kernel<<<dim3(FFD/32,  Cdim/32), 256>>>(ff1w, ff1T, Cdim, FFD);
    wT_kernel<<<dim3(Cdim/32, FFH/32),  256>>>(ff2w, ff2T, FFH, Cdim);
    wT_kernel<<<dim3(Cdim/32, Cdim/32), 256>>>(prw,  prwT, Cdim, Cdim);
    f2h_kernel<<<(MCTX * CTXD / 4 + 255) / 256, 256>>>(ctx, ctx16, MCTX * CTXD / 4);

    const dim3 gemm640(Cdim / 128, Mrows / 128);           // (5, 64)
    const dim3 gemmQKV(1920 / 128, Mrows / 128);           // (15, 64)
    const dim3 gemmKV(1280 / 128, (MCTX + 127) / 128);     // (10, 5)
    const dim3 gemmFF(FFD / 128, Mrows / 128);             // (40, 64)

    // y = proj_in(group_norm(x))
    groupnorm_kernel<<<Bn * 32, 256>>>(x, gn_g, gn_b, ln16);
    hgemm_kernel<<<gemm640, 256, GEMM_SMEM>>>(ln16, piwT, pib, nullptr, y, nullptr,
                                              Mrows, Cdim, Cdim);

    // self attention (fused QKV fp16, row stride 1920)
    layernorm_kernel<<<Mrows / 8, 256>>>(y, ln1g, ln1b, ln16, Mrows);
    hgemm_kernel<<<gemmQKV, 256, GEMM_SMEM>>>(ln16, wpT, nullptr, nullptr, nullptr, qkv16,
                                              Mrows, 1920, Cdim);
    attn_scores_h<<<dim3(16, 16, 64), 128>>>(qkv16, qkv16 + 640, sc, Sq, Sq, 1920, 1920);
    softmax_h<<<(64 * Sq) / 8, 256>>>(sc, p16, 64 * Sq, Sq, Sq);
    attn_pv_h<<<dim3(8, 1, 64), 256>>>(p16, qkv16 + 1280, at16, Sq, Sq, 1920);
    hgemm_kernel<<<gemm640, 256, GEMM_SMEM>>>(at16, a1oT, a1ob, y, t, nullptr,
                                              Mrows, Cdim, Cdim);

    // cross attention (fused KV fp16, row stride 1280)
    layernorm_kernel<<<Mrows / 8, 256>>>(t, ln2g, ln2b, ln16, Mrows);
    hgemm_kernel<<<gemmKV, 256, GEMM_SMEM>>>(ctx16, wcT, nullptr, nullptr, nullptr, kv16,
                                             MCTX, 1280, CTXD);
    hgemm_kernel<<<gemm640, 256, GEMM_SMEM>>>(ln16, a2qT, nullptr, nullptr, nullptr, q16,
                                              Mrows, Cdim, Cdim);
    attn_scores_h<<<dim3(2, 16, 64), 128>>>(q16, kv16, sc, Tctx, TPAD, Cdim, 1280);
    softmax_h<<<(64 * Sq) / 8, 256>>>(sc, p16, 64 * Sq, Tctx, TPAD);
    attn_pv_h<<<dim3(8, 1, 64), 256>>>(p16, kv16 + 640, at16, Tctx, TPAD, 1280);
    hgemm_kernel<<<gemm640, 256, GEMM_SMEM>>>(at16, a2oT, a2ob, t, t, nullptr,
                                              Mrows, Cdim, Cdim);

    // GEGLU feed-forward
    layernorm_kernel<<<Mrows / 8, 256>>>(t, ln3g, ln3b, ln16, Mrows);
    hgemm_kernel<<<gemmFF, 256, GEMM_SMEM>>>(ln16, ff1T, ff1b, nullptr, nullptr, ff16,
                                             Mrows, FFD, Cdim);
    geglu_h<<<(Mrows * (FFH / 8) + 255) / 256, 256>>>(ff16, gg16);
    hgemm_kernel<<<gemm640, 256, GEMM_SMEM>>>(gg16, ff2T, ff2b, t, t, nullptr,
                                              Mrows, Cdim, FFH);

    // proj_out + input residual
    f2h_kernel<<<(Mrows * Cdim / 4 + 255) / 256, 256>>>(t, t16, Mrows * Cdim / 4);
    hgemm_kernel<<<gemm640, 256, GEMM_SMEM>>>(t16, prwT, prb, x, out, nullptr,
                                              Mrows, Cdim, Cdim);
}

// round 15
// speedup vs baseline: 2.2737x; 1.3819x over previous
#include <cuda_runtime.h>
#include <cuda_fp16.h>
#include <math.h>
#include <stdint.h>

// ---------------- problem dims ----------------
#define Bn    8
#define Sq    1024
#define Cdim  640
#define Tctx  77
#define CTXD  768
#define NHEAD 8
#define HSZ   80
#define FFD   5120
#define FFH   2560
#define Mrows (Bn * Sq)      // 8192
#define MCTX  (Bn * Tctx)    // 616

// ---------------- scratch ----------------
__device__ float  g_y   [(size_t)Mrows * Cdim];
__device__ float  g_t   [(size_t)Mrows * Cdim];
__device__ __half g_ln16[(size_t)Mrows * Cdim];
__device__ __half g_q16 [(size_t)Mrows * Cdim];
__device__ __half g_at16[(size_t)Mrows * Cdim];
__device__ __half g_t16 [(size_t)Mrows * Cdim];
__device__ __half g_ctx16[(size_t)MCTX * CTXD];
__device__ __half g_qkv16[(size_t)Mrows * 1920];
__device__ __half g_kv16 [(size_t)MCTX * 1280];
__device__ __half g_ff16 [(size_t)Mrows * FFD];
__device__ __half g_gg16 [(size_t)Mrows * FFH];
// transposed fp16 weights [N][K]
__device__ __half g_piwT[(size_t)Cdim * Cdim];
__device__ __half g_wpT [(size_t)1920 * Cdim];
__device__ __half g_a2qT[(size_t)Cdim * Cdim];
__device__ __half g_wcT [(size_t)1280 * CTXD];
__device__ __half g_a1oT[(size_t)Cdim * Cdim];
__device__ __half g_a2oT[(size_t)Cdim * Cdim];
__device__ __half g_ff1T[(size_t)FFD * Cdim];
__device__ __half g_ff2T[(size_t)Cdim * FFH];
__device__ __half g_prwT[(size_t)Cdim * Cdim];

// ---------------- helpers ----------------
__device__ __forceinline__ void mma_f16(float* c, const uint32_t* a, const uint32_t* b)
{
    asm volatile(
        "mma.sync.aligned.m16n8k16.row.col.f32.f16.f16.f32 "
        "{%0,%1,%2,%3}, {%4,%5,%6,%7}, {%8,%9}, {%0,%1,%2,%3};"
        : "+f"(c[0]), "+f"(c[1]), "+f"(c[2]), "+f"(c[3])
        : "r"(a[0]), "r"(a[1]), "r"(a[2]), "r"(a[3]), "r"(b[0]), "r"(b[1]));
}

__device__ __forceinline__ void cp16(uint32_t dst, const void* src, bool pred)
{
    const int sz = pred ? 16 : 0;
    asm volatile("cp.async.cg.shared.global [%0], [%1], 16, %2;\n"
                 :: "r"(dst), "l"(src), "r"(sz));
}
__device__ __forceinline__ void cp_commit() { asm volatile("cp.async.commit_group;\n"); }
template <int N>
__device__ __forceinline__ void cp_wait() { asm volatile("cp.async.wait_group %0;\n" :: "n"(N)); }

__device__ __forceinline__ uint32_t pack2(float a, float b)
{
    __half2 h = __floats2half2_rn(a, b);
    return *reinterpret_cast<uint32_t*>(&h);
}

// ---------------- weight transpose+convert: fp32 [K][N] -> fp16 [N][K] ----------------
__global__ void wT_kernel(const float* __restrict__ in, __half* __restrict__ out, int K, int N)
{
    __shared__ float t[32][33];
    const int kt = blockIdx.y * 32, nt = blockIdx.x * 32;
    const int tx = threadIdx.x & 31, ty = threadIdx.x >> 5;
    #pragma unroll
    for (int r = ty; r < 32; r += 8)
        t[r][tx] = in[(size_t)(kt + r) * N + nt + tx];
    __syncthreads();
    #pragma unroll
    for (int r = ty; r < 32; r += 8)
        out[(size_t)(nt + r) * K + kt + tx] = __float2half(t[tx][r]);
}

// ---------------- fp32 -> fp16 (count multiple of 4) ----------------
__global__ void f2h_kernel(const float* __restrict__ in, __half* __restrict__ out, int n4)
{
    const int i = blockIdx.x * blockDim.x + threadIdx.x;
    if (i >= n4) return;
    const float4 v = *reinterpret_cast<const float4*>(in + (size_t)i * 4);
    uint2 u; u.x = pack2(v.x, v.y); u.y = pack2(v.z, v.w);
    *reinterpret_cast<uint2*>(out + (size_t)i * 4) = u;
}

// ---------------- GroupNorm (fp32 in, fp16 out) ----------------
__global__ void groupnorm_kernel(const float* __restrict__ x,
                                 const float* __restrict__ gamma,
                                 const float* __restrict__ beta,
                                 __half* __restrict__ out)
{
    const int b = blockIdx.x >> 5;
    const int g = blockIdx.x & 31;
    const float* base = x + (size_t)b * Sq * Cdim + g * 20;
    float sum = 0.f, sq = 0.f;
    for (int idx = threadIdx.x; idx < Sq * 20; idx += 256) {
        int hw = idx / 20, c = idx % 20;
        float v = base[(size_t)hw * Cdim + c];
        sum += v; sq += v * v;
    }
    #pragma unroll
    for (int o = 16; o > 0; o >>= 1) {
        sum += __shfl_xor_sync(0xffffffffu, sum, o);
        sq  += __shfl_xor_sync(0xffffffffu, sq,  o);
    }
    __shared__ float s1[8], s2[8];
    const int wid = threadIdx.x >> 5, lane = threadIdx.x & 31;
    if (lane == 0) { s1[wid] = sum; s2[wid] = sq; }
    __syncthreads();
    float tot = 0.f, totq = 0.f;
    #pragma unroll
    for (int i = 0; i < 8; i++) { tot += s1[i]; totq += s2[i]; }
    const float mean = tot * (1.f / 20480.f);
    const float var  = totq * (1.f / 20480.f) - mean * mean;
    const float rstd = rsqrtf(var + 1e-5f);
    __half* ob = out + (size_t)b * Sq * Cdim + g * 20;
    for (int idx = threadIdx.x; idx < Sq * 20; idx += 256) {
        int hw = idx / 20, c = idx % 20;
        float v = base[(size_t)hw * Cdim + c];
        ob[(size_t)hw * Cdim + c] =
            __float2half((v - mean) * rstd * gamma[g * 20 + c] + beta[g * 20 + c]);
    }
}

// ---------------- LayerNorm (fp32 in, fp16 out) ----------------
__global__ void layernorm_kernel(const float* __restrict__ x,
                                 const float* __restrict__ g,
                                 const float* __restrict__ b,
                                 __half* __restrict__ out, int rows)
{
    const int w = (blockIdx.x << 3) + (threadIdx.x >> 5);
    if (w >= rows) return;
    const int lane = threadIdx.x & 31;
    const float* row = x + (size_t)w * Cdim;
    float4 v[5];
    float sum = 0.f, sq = 0.f;
    #pragma unroll
    for (int p = 0; p < 5; p++) {
        v[p] = *reinterpret_cast<const float4*>(row + (lane + 32 * p) * 4);
        sum += v[p].x + v[p].y + v[p].z + v[p].w;
        sq  += v[p].x * v[p].x + v[p].y * v[p].y + v[p].z * v[p].z + v[p].w * v[p].w;
    }
    #pragma unroll
    for (int o = 16; o > 0; o >>= 1) {
        sum += __shfl_xor_sync(0xffffffffu, sum, o);
        sq  += __shfl_xor_sync(0xffffffffu, sq,  o);
    }
    const float mean = sum * (1.f / 640.f);
    const float var  = sq * (1.f / 640.f) - mean * mean;
    const float rstd = rsqrtf(var + 1e-5f);
    __half* orow = out + (size_t)w * Cdim;
    #pragma unroll
    for (int p = 0; p < 5; p++) {
        const int off = (lane + 32 * p) * 4;
        const float4 g4 = *reinterpret_cast<const float4*>(g + off);
        const float4 b4 = *reinterpret_cast<const float4*>(b + off);
        uint2 u;
        u.x = pack2((v[p].x - mean) * rstd * g4.x + b4.x,
                    (v[p].y - mean) * rstd * g4.y + b4.y);
        u.y = pack2((v[p].z - mean) * rstd * g4.z + b4.z,
                    (v[p].w - mean) * rstd * g4.w + b4.w);
        *reinterpret_cast<uint2*>(orow + off) = u;
    }
}

// ---------------- pipelined FP16 GEMM ----------------
#define HP   40
#define HP2  20
#define STGH (128 * HP)
#define STGB (STGH * 2)
#define NSTAGE 3
#define GEMM_SMEM (NSTAGE * 2 * STGB)

__global__ __launch_bounds__(256, 2)
void hgemm_kernel(const __half* __restrict__ A, const __half* __restrict__ Bt,
                  const float* __restrict__ bias, const float* __restrict__ Res,
                  float* __restrict__ C32, __half* __restrict__ C16,
                  int M, int N, int K)
{
    extern __shared__ __half smem[];
    __half* As = smem;
    __half* Bs = smem + NSTAGE * STGH;
    const int tid  = threadIdx.x;
    const int lane = tid & 31, warp = tid >> 5;
    const int g = lane >> 2, tig = lane & 3;
    const int wm = (warp >> 2) * 64;
    const int wn = (warp & 3) * 32;
    const int row0 = blockIdx.y * 128, col0 = blockIdx.x * 128;

    const int srow = tid >> 1, soff = (tid & 1) * 16;
    const bool arow_ok = (row0 + srow) < M;
    const __half* agp = A  + (size_t)(row0 + srow) * K + soff;
    const __half* bgp = Bt + (size_t)(col0 + srow) * K + soff;
    const uint32_t as_d = (uint32_t)__cvta_generic_to_shared(As + srow * HP + soff);
    const uint32_t bs_d = (uint32_t)__cvta_generic_to_shared(Bs + srow * HP + soff);

    float acc[4][4][4];
    #pragma unroll
    for (int mt = 0; mt < 4; mt++)
        #pragma unroll
        for (int nt = 0; nt < 4; nt++)
            #pragma unroll
            for (int i = 0; i < 4; i++) acc[mt][nt][i] = 0.f;

    const int KT = K >> 5;

    #pragma unroll
    for (int p = 0; p < 2; p++) {
        if (p < KT) {
            const __half* ag = agp + p * 32;
            const __half* bg = bgp + p * 32;
            #pragma unroll
            for (int l = 0; l < 2; l++) cp16(as_d + (uint32_t)(p * STGB) + l * 16, ag + l * 8, arow_ok);
            #pragma unroll
            for (int l = 0; l < 2; l++) cp16(bs_d + (uint32_t)(p * STGB) + l * 16, bg + l * 8, true);
        }
        cp_commit();
    }

    int s = 0, sw = 2;
    for (int kt = 0; kt < KT; kt++) {
        cp_wait<1>();
        __syncthreads();

        if (kt + 2 < KT) {
            const __half* ag = agp + (kt + 2) * 32;
            const __half* bg = bgp + (kt + 2) * 32;
            const uint32_t ad = as_d + (uint32_t)(sw * STGB);
            const uint32_t bd = bs_d + (uint32_t)(sw * STGB);
            #pragma unroll
            for (int l = 0; l < 2; l++) cp16(ad + l * 16, ag + l * 8, arow_ok);
            #pragma unroll
            for (int l = 0; l < 2; l++) cp16(bd + l * 16, bg + l * 8, true);
        }
        cp_commit();

        const uint32_t* as32 = reinterpret_cast<const uint32_t*>(As + s * STGH);
        const uint32_t* bs32 = reinterpret_cast<const uint32_t*>(Bs + s * STGH);
        #pragma unroll
        for (int ks = 0; ks < 2; ks++) {
            const int k2 = ks * 8 + tig;
            uint32_t af[4][4];
            #pragma unroll
            for (int mt = 0; mt < 4; mt++) {
                const int m = wm + mt * 16 + g;
                af[mt][0] = as32[m * HP2 + k2];
                af[mt][1] = as32[(m + 8) * HP2 + k2];
                af[mt][2] = as32[m * HP2 + k2 + 4];
                af[mt][3] = as32[(m + 8) * HP2 + k2 + 4];
            }
            uint32_t bf[4][2];
            #pragma unroll
            for (int nt = 0; nt < 4; nt++) {
                const int n = wn + nt * 8 + g;
                bf[nt][0] = bs32[n * HP2 + k2];
                bf[nt][1] = bs32[n * HP2 + k2 + 4];
            }
            #pragma unroll
            for (int mt = 0; mt < 4; mt++)
                #pragma unroll
                for (int nt = 0; nt < 4; nt++)
                    mma_f16(acc[mt][nt], af[mt], bf[nt]);
        }

        s = (s == NSTAGE - 1) ? 0 : s + 1;
        sw = (sw == NSTAGE - 1) ? 0 : sw + 1;
    }

    #pragma unroll
    for (int mt = 0; mt < 4; mt++) {
        const int r0 = row0 + wm + mt * 16 + g;
        const int r1 = r0 + 8;
        #pragma unroll
        for (int nt = 0; nt < 4; nt++) {
            const int c = col0 + wn + nt * 8 + 2 * tig;
            float2 v0 = make_float2(acc[mt][nt][0], acc[mt][nt][1]);
            float2 v1 = make_float2(acc[mt][nt][2], acc[mt][nt][3]);
            if (bias) {
                const float2 bb = *reinterpret_cast<const float2*>(bias + c);
                v0.x += bb.x; v0.y += bb.y;
                v1.x += bb.x; v1.y += bb.y;
            }
            if (r0 < M) {
                if (Res) {
                    const float2 rv = *reinterpret_cast<const float2*>(Res + (size_t)r0 * N + c);
                    v0.x += rv.x; v0.y += rv.y;
                }
                if (C32) *reinterpret_cast<float2*>(C32 + (size_t)r0 * N + c) = v0;
                if (C16) *reinterpret_cast<uint32_t*>(C16 + (size_t)r0 * N + c) = pack2(v0.x, v0.y);
            }
            if (r1 < M) {
                if (Res) {
                    const float2 rv = *reinterpret_cast<const float2*>(Res + (size_t)r1 * N + c);
                    v1.x += rv.x; v1.y += rv.y;
                }
                if (C32) *reinterpret_cast<float2*>(C32 + (size_t)r1 * N + c) = v1;
                if (C16) *reinterpret_cast<uint32_t*>(C16 + (size_t)r1 * N + c) = pack2(v1.x, v1.y);
            }
        }
    }
}

// ---------------- fused flash attention (fp16 in/out, fp32 softmax state) ----------------
// Block: 64 q-rows, 4 warps x 16 rows each; full 80-wide head per warp.
#define FQP  88
#define FQP2 44
#define FVP  72
#define FVP2 36
__global__ __launch_bounds__(128)
void flash_attn(const __half* __restrict__ Q, const __half* __restrict__ K,
                const __half* __restrict__ V, __half* __restrict__ O,
                int Tk, int qstr, int kstr, int kSeq)
{
    __shared__ __half Qs[64 * FQP];
    __shared__ __half Ks[64 * FQP];
    __shared__ __half Vs[80 * FVP];

    const int bh = blockIdx.y, b = bh >> 3, n = bh & 7;
    const __half* qb = Q + (size_t)b * Sq * qstr + n * HSZ;
    const __half* kb = K + (size_t)b * kSeq * kstr + n * HSZ;
    const __half* vb = V + (size_t)b * kSeq * kstr + n * HSZ;
    __half* ob = O + (size_t)b * Sq * Cdim + n * HSZ;
    const int i0 = blockIdx.x * 64;
    const int tid = threadIdx.x;
    const int lane = tid & 31, warp = tid >> 5;
    const int g = lane >> 2, tig = lane & 3;
    const int wq = warp * 16;

    // stage Q once
    for (int e = tid; e < 64 * 10; e += 128) {
        const int r = e / 10, c8 = (e % 10) * 8;
        *reinterpret_cast<uint4*>(&Qs[r * FQP + c8]) =
            *reinterpret_cast<const uint4*>(qb + (size_t)(i0 + r) * qstr + c8);
    }
    __syncthreads();

    // Q fragments: rows [wq, wq+16), 5 k16 chunks
    uint32_t qf[5][4];
    {
        const uint32_t* qs32 = reinterpret_cast<const uint32_t*>(Qs);
        #pragma unroll
        for (int ks = 0; ks < 5; ks++) {
            const int k2 = ks * 8 + tig;
            qf[ks][0] = qs32[(wq + g) * FQP2 + k2];
            qf[ks][1] = qs32[(wq + g + 8) * FQP2 + k2];
            qf[ks][2] = qs32[(wq + g) * FQP2 + k2 + 4];
            qf[ks][3] = qs32[(wq + g + 8) * FQP2 + k2 + 4];
        }
    }

    float m0 = -1e30f, m1 = -1e30f, l0 = 0.f, l1 = 0.f;
    float oacc[10][4];
    #pragma unroll
    for (int nt = 0; nt < 10; nt++)
        #pragma unroll
        for (int i = 0; i < 4; i++) oacc[nt][i] = 0.f;

    const float scale = 0.11180339887498949f;
    const int nT = (Tk + 63) / 64;

    for (int jt = 0; jt < nT; jt++) {
        __syncthreads();
        // stage K tile [64 x 80] and V^T tile [80 x 64]
        for (int e = tid; e < 64 * 10; e += 128) {
            const int r = e / 10, c8 = (e % 10) * 8;
            uint4 kv = make_uint4(0u, 0u, 0u, 0u);
            if (jt * 64 + r < Tk)
                kv = *reinterpret_cast<const uint4*>(kb + (size_t)(jt * 64 + r) * kstr + c8);
            *reinterpret_cast<uint4*>(&Ks[r * FQP + c8]) = kv;
            uint4 vv = make_uint4(0u, 0u, 0u, 0u);
            if (jt * 64 + r < Tk)
                vv = *reinterpret_cast<const uint4*>(vb + (size_t)(jt * 64 + r) * kstr + c8);
            const __half* vh = reinterpret_cast<const __half*>(&vv);
            #pragma unroll
            for (int i = 0; i < 8; i++)
                Vs[(c8 + i) * FVP + r] = vh[i];
        }
        __syncthreads();

        // S = scale * Q K^T  (16 x 64 per warp)
        float sacc[8][4];
        #pragma unroll
        for (int nt = 0; nt < 8; nt++)
            #pragma unroll
            for (int i = 0; i < 4; i++) sacc[nt][i] = 0.f;
        {
            const uint32_t* ks32 = reinterpret_cast<const uint32_t*>(Ks);
            #pragma unroll
            for (int ks = 0; ks < 5; ks++) {
                const int k2 = ks * 8 + tig;
                uint32_t bf[8][2];
                #pragma unroll
                for (int nt = 0; nt < 8; nt++) {
                    const int nn = nt * 8 + g;
                    bf[nt][0] = ks32[nn * FQP2 + k2];
                    bf[nt][1] = ks32[nn * FQP2 + k2 + 4];
                }
                #pragma unroll
                for (int nt = 0; nt < 8; nt++)
                    mma_f16(sacc[nt], qf[ks], bf[nt]);
            }
        }

        // scale + mask, row max
        float rm0 = -1e30f, rm1 = -1e30f;
        #pragma unroll
        for (int nt = 0; nt < 8; nt++) {
            const int cb = jt * 64 + nt * 8 + 2 * tig;
            sacc[nt][0] = (cb     < Tk) ? sacc[nt][0] * scale : -1e30f;
            sacc[nt][1] = (cb + 1 < Tk) ? sacc[nt][1] * scale : -1e30f;
            sacc[nt][2] = (cb     < Tk) ? sacc[nt][2] * scale : -1e30f;
            sacc[nt][3] = (cb + 1 < Tk) ? sacc[nt][3] * scale : -1e30f;
            rm0 = fmaxf(rm0, fmaxf(sacc[nt][0], sacc[nt][1]));
            rm1 = fmaxf(rm1, fmaxf(sacc[nt][2], sacc[nt][3]));
        }
        rm0 = fmaxf(rm0, __shfl_xor_sync(0xffffffffu, rm0, 1));
        rm0 = fmaxf(rm0, __shfl_xor_sync(0xffffffffu, rm0, 2));
        rm1 = fmaxf(rm1, __shfl_xor_sync(0xffffffffu, rm1, 1));
        rm1 = fmaxf(rm1, __shfl_xor_sync(0xffffffffu, rm1, 2));

        const float mn0 = fmaxf(m0, rm0), mn1 = fmaxf(m1, rm1);
        const float a0 = __expf(m0 - mn0), a1 = __expf(m1 - mn1);
        m0 = mn0; m1 = mn1;

        float rs0 = 0.f, rs1 = 0.f;
        #pragma unroll
        for (int nt = 0; nt < 8; nt++) {
            sacc[nt][0] = __expf(sacc[nt][0] - m0);
            sacc[nt][1] = __expf(sacc[nt][1] - m0);
            sacc[nt][2] = __expf(sacc[nt][2] - m1);
            sacc[nt][3] = __expf(sacc[nt][3] - m1);
            rs0 += sacc[nt][0] + sacc[nt][1];
            rs1 += sacc[nt][2] + sacc[nt][3];
        }
        rs0 += __shfl_xor_sync(0xffffffffu, rs0, 1);
        rs0 += __shfl_xor_sync(0xffffffffu, rs0, 2);
        rs1 += __shfl_xor_sync(0xffffffffu, rs1, 1);
        rs1 += __shfl_xor_sync(0xffffffffu, rs1, 2);
        l0 = l0 * a0 + rs0;
        l1 = l1 * a1 + rs1;

        #pragma unroll
        for (int nt = 0; nt < 10; nt++) {
            oacc[nt][0] *= a0; oacc[nt][1] *= a0;
            oacc[nt][2] *= a1; oacc[nt][3] *= a1;
        }

        // O += P V  (P a-frags from sacc: chunk t = n-tiles 2t, 2t+1)
        {
            const uint32_t* vs32 = reinterpret_cast<const uint32_t*>(Vs);
            #pragma unroll
            for (int t = 0; t < 4; t++) {
                uint32_t pf[4];
                pf[0] = pack2(sacc[2 * t][0],     sacc[2 * t][1]);
                pf[1] = pack2(sacc[2 * t][2],     sacc[2 * t][3]);
                pf[2] = pack2(sacc[2 * t + 1][0], sacc[2 * t + 1][1]);
                pf[3] = pack2(sacc[2 * t + 1][2], sacc[2 * t + 1][3]);
                const int k2 = t * 8 + tig;
                #pragma unroll
                for (int nt = 0; nt < 10; nt++) {
                    const int nn = nt * 8 + g;
                    uint32_t bf[2];
                    bf[0] = vs32[nn * FVP2 + k2];
                    bf[1] = vs32[nn * FVP2 + k2 + 4];
                    mma_f16(oacc[nt], pf, bf);
                }
            }
        }
    }

    // finalize: O / l, write fp16 (full 80 cols)
    const float il0 = 1.f / l0, il1 = 1.f / l1;
    const int r0 = i0 + wq + g, r1 = r0 + 8;
    #pragma unroll
    for (int nt = 0; nt < 10; nt++) {
        const int c = nt * 8 + 2 * tig;
        *reinterpret_cast<uint32_t*>(ob + (size_t)r0 * Cdim + c) =
            pack2(oacc[nt][0] * il0, oacc[nt][1] * il0);
        *reinterpret_cast<uint32_t*>(ob + (size_t)r1 * Cdim + c) =
            pack2(oacc[nt][2] * il1, oacc[nt][3] * il1);
    }
}

// ---------------- GEGLU (fp16 in/out, fp32 math) ----------------
__device__ __forceinline__ float geglu_one(float xh, float g)
{
    const float t = tanhf(g * 0.7978845608f * (1.f + 0.044715f * g * g));
    return xh * 0.5f * g * (1.f + t);
}

__global__ void geglu_h(const __half* __restrict__ ff, __half* __restrict__ out)
{
    const size_t idx = (size_t)blockIdx.x * blockDim.x + threadIdx.x;
    if (idx >= (size_t)Mrows * (FFH / 8)) return;
    const size_t row = idx / (FFH / 8);
    const int c8 = (int)(idx % (FFH / 8)) * 8;
    const uint4 xh4 = *reinterpret_cast<const uint4*>(ff + row * FFD + c8);
    const uint4 gt4 = *reinterpret_cast<const uint4*>(ff + row * FFD + FFH + c8);
    const __half2* xh = reinterpret_cast<const __half2*>(&xh4);
    const __half2* gt = reinterpret_cast<const __half2*>(&gt4);
    uint4 o4;
    uint32_t* oh = reinterpret_cast<uint32_t*>(&o4);
    #pragma unroll
    for (int i = 0; i < 4; i++) {
        const float2 xf = __half22float2(xh[i]);
        const float2 gf = __half22float2(gt[i]);
        oh[i] = pack2(geglu_one(xf.x, gf.x), geglu_one(xf.y, gf.y));
    }
    *reinterpret_cast<uint4*>(out + row * FFH + c8) = o4;
}

// ---------------- host orchestration ----------------
extern "C" void kernel_launch(void* const* d_in, const int* in_sizes, int n_in,
                              void* d_out, int out_size)
{
    (void)in_sizes; (void)n_in; (void)out_size;
    const float* x     = (const float*)d_in[0];
    const float* ctx   = (const float*)d_in[1];
    const float* gn_g  = (const float*)d_in[2];
    const float* gn_b  = (const float*)d_in[3];
    const float* piw   = (const float*)d_in[4];
    const float* pib   = (const float*)d_in[5];
    const float* ln1g  = (const float*)d_in[6];
    const float* ln1b  = (const float*)d_in[7];
    const float* a1q   = (const float*)d_in[8];
    const float* a1k   = (const float*)d_in[9];
    const float* a1v   = (const float*)d_in[10];
    const float* a1o   = (const float*)d_in[11];
    const float* a1ob  = (const float*)d_in[12];
    const float* ln2g  = (const float*)d_in[13];
    const float* ln2b  = (const float*)d_in[14];
    const float* a2q   = (const float*)d_in[15];
    const float* a2k   = (const float*)d_in[16];
    const float* a2v   = (const float*)d_in[17];
    const float* a2o   = (const float*)d_in[18];
    const float* a2ob  = (const float*)d_in[19];
    const float* ln3g  = (const float*)d_in[20];
    const float* ln3b  = (const float*)d_in[21];
    const float* ff1w  = (const float*)d_in[22];
    const float* ff1b  = (const float*)d_in[23];
    const float* ff2w  = (const float*)d_in[24];
    const float* ff2b  = (const float*)d_in[25];
    const float* prw   = (const float*)d_in[26];
    const float* prb   = (const float*)d_in[27];
    float* out = (float*)d_out;

    float *y, *t;
    __half *ln16, *q16, *at16, *t16, *ctx16, *qkv16, *kv16, *ff16, *gg16;
    __half *piwT, *wpT, *a2qT, *wcT, *a1oT, *a2oT, *ff1T, *ff2T, *prwT;
    cudaGetSymbolAddress((void**)&y,    g_y);
    cudaGetSymbolAddress((void**)&t,    g_t);
    cudaGetSymbolAddress((void**)&ln16, g_ln16);
    cudaGetSymbolAddress((void**)&q16,  g_q16);
    cudaGetSymbolAddress((void**)&at16, g_at16);
    cudaGetSymbolAddress((void**)&t16,  g_t16);
    cudaGetSymbolAddress((void**)&ctx16,g_ctx16);
    cudaGetSymbolAddress((void**)&qkv16,g_qkv16);
    cudaGetSymbolAddress((void**)&kv16, g_kv16);
    cudaGetSymbolAddress((void**)&ff16, g_ff16);
    cudaGetSymbolAddress((void**)&gg16, g_gg16);
    cudaGetSymbolAddress((void**)&piwT, g_piwT);
    cudaGetSymbolAddress((void**)&wpT,  g_wpT);
    cudaGetSymbolAddress((void**)&a2qT, g_a2qT);
    cudaGetSymbolAddress((void**)&wcT,  g_wcT);
    cudaGetSymbolAddress((void**)&a1oT, g_a1oT);
    cudaGetSymbolAddress((void**)&a2oT, g_a2oT);
    cudaGetSymbolAddress((void**)&ff1T, g_ff1T);
    cudaGetSymbolAddress((void**)&ff2T, g_ff2T);
    cudaGetSymbolAddress((void**)&prwT, g_prwT);

    cudaFuncSetAttribute(hgemm_kernel,
                         cudaFuncAttributeMaxDynamicSharedMemorySize, GEMM_SMEM);

    // ---- weight transpose+convert ----
    wT_kernel<<<dim3(Cdim/32, Cdim/32), 256>>>(piw,  piwT, Cdim, Cdim);
    wT_kernel<<<dim3(Cdim/32, Cdim/32), 256>>>(a1q,  wpT,                       Cdim, Cdim);
    wT_kernel<<<dim3(Cdim/32, Cdim/32), 256>>>(a1k,  wpT + (size_t)640 * Cdim,  Cdim, Cdim);
    wT_kernel<<<dim3(Cdim/32, Cdim/32), 256>>>(a1v,  wpT + (size_t)1280 * Cdim, Cdim, Cdim);
    wT_kernel<<<dim3(Cdim/32, Cdim/32), 256>>>(a2q,  a2qT, Cdim, Cdim);
    wT_kernel<<<dim3(Cdim/32, CTXD/32), 256>>>(a2k,  wcT,                       CTXD, Cdim);
    wT_kernel<<<dim3(Cdim/32, CTXD/32), 256>>>(a2v,  wcT + (size_t)640 * CTXD,  CTXD, Cdim);
    wT_kernel<<<dim3(Cdim/32, Cdim/32), 256>>>(a1o,  a1oT, Cdim, Cdim);
    wT_kernel<<<dim3(Cdim/32, Cdim/32), 256>>>(a2o,  a2oT, Cdim, Cdim);
    wT_kernel<<<dim3(FFD/32,  Cdim/32), 256>>>(ff1w, ff1T, Cdim, FFD);
    wT_kernel<<<dim3(Cdim/32, FFH/32),  256>>>(ff2w, ff2T, FFH, Cdim);
    wT_kernel<<<dim3(Cdim/32, Cdim/32), 256>>>(prw,  prwT, Cdim, Cdim);
    f2h_kernel<<<(MCTX * CTXD / 4 + 255) / 256, 256>>>(ctx, ctx16, MCTX * CTXD / 4);

    const dim3 gemm640(Cdim / 128, Mrows / 128);
    const dim3 gemmQKV(1920 / 128, Mrows / 128);
    const dim3 gemmKV(1280 / 128, (MCTX + 127) / 128);
    const dim3 gemmFF(FFD / 128, Mrows / 128);

    // y = proj_in(group_norm(x))
    groupnorm_kernel<<<Bn * 32, 256>>>(x, gn_g, gn_b, ln16);
    hgemm_kernel<<<gemm640, 256, GEMM_SMEM>>>(ln16, piwT, pib, nullptr, y, nullptr,
                                              Mrows, Cdim, Cdim);

    // self attention (fused QKV + flash)
    layernorm_kernel<<<Mrows / 8, 256>>>(y, ln1g, ln1b, ln16, Mrows);
    hgemm_kernel<<<gemmQKV, 256, GEMM_SMEM>>>(ln16, wpT, nullptr, nullptr, nullptr, qkv16,
                                              Mrows, 1920, Cdim);
    flash_attn<<<dim3(Sq / 64, 64), 128>>>(qkv16, qkv16 + 640, qkv16 + 1280, at16,
                                           Sq, 1920, 1920, Sq);
    hgemm_kernel<<<gemm640, 256, GEMM_SMEM>>>(at16, a1oT, a1ob, y, t, nullptr,
                                              Mrows, Cdim, Cdim);

    // cross attention (fused KV + flash)
    layernorm_kernel<<<Mrows / 8, 256>>>(t, ln2g, ln2b, ln16, Mrows);
    hgemm_kernel<<<gemmKV, 256, GEMM_SMEM>>>(ctx16, wcT, nullptr, nullptr, nullptr, kv16,
                                             MCTX, 1280, CTXD);
    hgemm_kernel<<<gemm640, 256, GEMM_SMEM>>>(ln16, a2qT, nullptr, nullptr, nullptr, q16,
                                              Mrows, Cdim, Cdim);
    flash_attn<<<dim3(Sq / 64, 64), 128>>>(q16, kv16, kv16 + 640, at16,
                                           Tctx, Cdim, 1280, Tctx);
    hgemm_kernel<<<gemm640, 256, GEMM_SMEM>>>(at16, a2oT, a2ob, t, t, nullptr,
                                              Mrows, Cdim, Cdim);

    // GEGLU feed-forward (ff2 writes fp32 t and fp16 t16 in one pass)
    layernorm_kernel<<<Mrows / 8, 256>>>(t, ln3g, ln3b, ln16, Mrows);
    hgemm_kernel<<<gemmFF, 256, GEMM_SMEM>>>(ln16, ff1T, ff1b, nullptr, nullptr, ff16,
                                             Mrows, FFD, Cdim);
    geglu_h<<<(Mrows * (FFH / 8) + 255) / 256, 256>>>(ff16, gg16);
    hgemm_kernel<<<gemm640, 256, GEMM_SMEM>>>(gg16, ff2T, ff2b, t, t, t16,
                                              Mrows, Cdim, FFH);

    // proj_out + input residual
    hgemm_kernel<<<gemm640, 256, GEMM_SMEM>>>(t16, prwT, prb, x, out, nullptr,
                                              Mrows, Cdim, Cdim);
}